// round 1
// baseline (speedup 1.0000x reference)
#include <cuda_runtime.h>
#include <cuda_bf16.h>
#include <math.h>

#define BATCH  4
#define SEQ    1024
#define DMODEL 1024
#define NHEAD  16
#define DHEAD  64
#define NTOK   (BATCH * SEQ)

// Scratch (device globals; no runtime allocation allowed).
// Q/K/V stored as [B, H, S, DK]; C (attention context) as [B, S, D].
__device__ float g_Q[NTOK * DMODEL];
__device__ float g_K[NTOK * DMODEL];
__device__ float g_V[NTOK * DMODEL];
__device__ float g_C[NTOK * DMODEL];

// ---------------------------------------------------------------------------
// SGEMM: out[n, m] = sum_k A[n,k] * W[m,k] + bias[m]
// A: [4096, 1024] row-major, W: [1024, 1024] row-major (acts as B^T).
// 128x128 block tile, BK=8, 256 threads, 8x8 per-thread register tile.
// scatter=1: write out as [B,H,S,DK] (QKV). scatter=0: plain [N, M].
// ---------------------------------------------------------------------------
__global__ __launch_bounds__(256) void sgemm_kernel(
    const float* __restrict__ A, const float* __restrict__ W,
    const float* __restrict__ bias, float* __restrict__ out, int scatter)
{
    __shared__ float As[8][128];
    __shared__ float Bs[8][128];

    const int tid  = threadIdx.x;
    const int tx   = tid & 15;
    const int ty   = tid >> 4;
    const int brow = blockIdx.y * 128;
    const int bcol = blockIdx.x * 128;

    // Cooperative loads: thread -> one float4 of A-tile and one of W-tile.
    const int lr = tid >> 1;        // 0..127
    const int lk = (tid & 1) * 4;   // 0 or 4
    const float* Ap = A + (size_t)(brow + lr) * DMODEL + lk;
    const float* Wp = W + (size_t)(bcol + lr) * DMODEL + lk;

    float acc[8][8];
#pragma unroll
    for (int i = 0; i < 8; i++)
#pragma unroll
        for (int j = 0; j < 8; j++) acc[i][j] = 0.0f;

    for (int k0 = 0; k0 < DMODEL; k0 += 8) {
        float4 av = *(const float4*)(Ap + k0);
        float4 wv = *(const float4*)(Wp + k0);
        __syncthreads();
        As[lk + 0][lr] = av.x; As[lk + 1][lr] = av.y;
        As[lk + 2][lr] = av.z; As[lk + 3][lr] = av.w;
        Bs[lk + 0][lr] = wv.x; Bs[lk + 1][lr] = wv.y;
        Bs[lk + 2][lr] = wv.z; Bs[lk + 3][lr] = wv.w;
        __syncthreads();

#pragma unroll
        for (int kk = 0; kk < 8; kk++) {
            float a[8], b[8];
            *(float4*)&a[0] = *(const float4*)&As[kk][ty * 4];
            *(float4*)&a[4] = *(const float4*)&As[kk][64 + ty * 4];
            *(float4*)&b[0] = *(const float4*)&Bs[kk][tx * 4];
            *(float4*)&b[4] = *(const float4*)&Bs[kk][64 + tx * 4];
#pragma unroll
            for (int i = 0; i < 8; i++)
#pragma unroll
                for (int j = 0; j < 8; j++)
                    acc[i][j] = fmaf(a[i], b[j], acc[i][j]);
        }
    }

#pragma unroll
    for (int i = 0; i < 8; i++) {
        const int r = brow + ((i < 4) ? (ty * 4 + i) : (64 + ty * 4 + i - 4));
#pragma unroll
        for (int j = 0; j < 8; j++) {
            const int c = bcol + ((j < 4) ? (tx * 4 + j) : (64 + tx * 4 + j - 4));
            const float v = acc[i][j] + bias[c];
            if (scatter) {
                const int bi = r >> 10, s = r & 1023;
                const int h = c >> 6, dk = c & 63;
                out[(((size_t)(bi * NHEAD + h)) * SEQ + s) * DHEAD + dk] = v;
            } else {
                out[(size_t)r * DMODEL + c] = v;
            }
        }
    }
}

// ---------------------------------------------------------------------------
// Flash-style attention with mask|diag and post-softmax group_prob scaling.
// One block per (q-tile of 64, head, batch). 256 threads = 16x16.
// Thread (ty,tx): rows 4*ty..4*ty+3, cols/dims 4*tx..4*tx+3 (4x4 reg tiles).
// Online softmax: l accumulates exp(s-m); acc accumulates exp(s-m)*g*v.
// ---------------------------------------------------------------------------
#define TPAD 68
#define ATT_SMEM_FLOATS (4 * 64 * TPAD)
#define ATT_SMEM_BYTES  (ATT_SMEM_FLOATS * 4)

__global__ __launch_bounds__(256) void attn_kernel(
    const int* __restrict__ mask, const float* __restrict__ group)
{
    extern __shared__ float sm[];
    float* Qs = sm;                  // transposed: Qs[k*TPAD + row]
    float* Ks = sm + 64 * TPAD;      // transposed: Ks[k*TPAD + col]
    float* Vs = sm + 2 * 64 * TPAD;  // natural:    Vs[key*TPAD + dim]
    float* Ps = sm + 3 * 64 * TPAD;  // transposed: Ps[key*TPAD + row]

    const int tid = threadIdx.x;
    const int tx  = tid & 15;
    const int ty  = tid >> 4;
    const int b   = blockIdx.z;
    const int h   = blockIdx.y;
    const int q0  = blockIdx.x * 64;

    const float* Qg = g_Q + (((size_t)(b * NHEAD + h)) * SEQ + q0) * DHEAD;

    // Load Q tile (transposed into smem).
#pragma unroll
    for (int i = 0; i < 4; i++) {
        const int idx = tid * 4 + i;       // 0..1023
        const int r   = idx >> 4;          // 0..63
        const int c4  = (idx & 15) * 4;    // 0..60
        const float4 q = *(const float4*)(Qg + r * DHEAD + c4);
        Qs[(c4 + 0) * TPAD + r] = q.x;
        Qs[(c4 + 1) * TPAD + r] = q.y;
        Qs[(c4 + 2) * TPAD + r] = q.z;
        Qs[(c4 + 3) * TPAD + r] = q.w;
    }

    float m[4], l[4], acc[4][4];
#pragma unroll
    for (int i = 0; i < 4; i++) {
        m[i] = -INFINITY;
        l[i] = 0.0f;
#pragma unroll
        for (int j = 0; j < 4; j++) acc[i][j] = 0.0f;
    }

    const int qrow = q0 + ty * 4;

    for (int kt = 0; kt < SEQ / 64; kt++) {
        const int k0 = kt * 64;
        const float* Kg = g_K + (((size_t)(b * NHEAD + h)) * SEQ + k0) * DHEAD;
        const float* Vg = g_V + (((size_t)(b * NHEAD + h)) * SEQ + k0) * DHEAD;

        __syncthreads();  // previous tile's PV reads done before overwrite
#pragma unroll
        for (int i = 0; i < 4; i++) {
            const int idx = tid * 4 + i;
            const int r   = idx >> 4;
            const int c4  = (idx & 15) * 4;
            const float4 kv = *(const float4*)(Kg + r * DHEAD + c4);
            Ks[(c4 + 0) * TPAD + r] = kv.x;
            Ks[(c4 + 1) * TPAD + r] = kv.y;
            Ks[(c4 + 2) * TPAD + r] = kv.z;
            Ks[(c4 + 3) * TPAD + r] = kv.w;
            const float4 vv = *(const float4*)(Vg + r * DHEAD + c4);
            *(float4*)&Vs[r * TPAD + c4] = vv;
        }
        __syncthreads();

        // S = Q K^T (4x4 per thread)
        float s[4][4];
#pragma unroll
        for (int i = 0; i < 4; i++)
#pragma unroll
            for (int j = 0; j < 4; j++) s[i][j] = 0.0f;

#pragma unroll 8
        for (int k = 0; k < DHEAD; k++) {
            const float4 qa = *(const float4*)&Qs[k * TPAD + ty * 4];
            const float4 kb = *(const float4*)&Ks[k * TPAD + tx * 4];
            const float aa[4] = {qa.x, qa.y, qa.z, qa.w};
            const float bb[4] = {kb.x, kb.y, kb.z, kb.w};
#pragma unroll
            for (int i = 0; i < 4; i++)
#pragma unroll
                for (int j = 0; j < 4; j++)
                    s[i][j] = fmaf(aa[i], bb[j], s[i][j]);
        }

        // scale, mask|diag, fetch group_prob
        float g[4][4];
        const int kcol0 = k0 + tx * 4;
#pragma unroll
        for (int ii = 0; ii < 4; ii++) {
            const int q = qrow + ii;
            const size_t base = ((size_t)b * SEQ + q) * SEQ + kcol0;
            const int4   mk = *(const int4*)(mask + base);
            const float4 g4 = *(const float4*)(group + base);
            s[ii][0] = (mk.x || (q == kcol0 + 0)) ? s[ii][0] * 0.125f : -1e9f;
            s[ii][1] = (mk.y || (q == kcol0 + 1)) ? s[ii][1] * 0.125f : -1e9f;
            s[ii][2] = (mk.z || (q == kcol0 + 2)) ? s[ii][2] * 0.125f : -1e9f;
            s[ii][3] = (mk.w || (q == kcol0 + 3)) ? s[ii][3] * 0.125f : -1e9f;
            g[ii][0] = g4.x; g[ii][1] = g4.y; g[ii][2] = g4.z; g[ii][3] = g4.w;
        }

        // online softmax (row stats shared by the 16 threads of each row group)
        float p[4][4];
#pragma unroll
        for (int ii = 0; ii < 4; ii++) {
            float rm = fmaxf(fmaxf(s[ii][0], s[ii][1]), fmaxf(s[ii][2], s[ii][3]));
#pragma unroll
            for (int off = 8; off >= 1; off >>= 1)
                rm = fmaxf(rm, __shfl_xor_sync(0xffffffffu, rm, off, 16));
            const float mn = fmaxf(m[ii], rm);
            float rs = 0.0f;
#pragma unroll
            for (int jj = 0; jj < 4; jj++) {
                p[ii][jj] = __expf(s[ii][jj] - mn);
                rs += p[ii][jj];
            }
#pragma unroll
            for (int off = 8; off >= 1; off >>= 1)
                rs += __shfl_xor_sync(0xffffffffu, rs, off, 16);
            const float sc = __expf(m[ii] - mn);
            l[ii] = l[ii] * sc + rs;
            m[ii] = mn;
#pragma unroll
            for (int jj = 0; jj < 4; jj++) acc[ii][jj] *= sc;
        }

        // P (already * group_prob) to smem, transposed [key][row]
#pragma unroll
        for (int ii = 0; ii < 4; ii++)
#pragma unroll
            for (int jj = 0; jj < 4; jj++)
                Ps[(tx * 4 + jj) * TPAD + ty * 4 + ii] = p[ii][jj] * g[ii][jj];
        __syncthreads();

        // acc += P @ V
#pragma unroll 8
        for (int i = 0; i < 64; i++) {
            const float4 pa = *(const float4*)&Ps[i * TPAD + ty * 4];
            const float4 vb = *(const float4*)&Vs[i * TPAD + tx * 4];
            const float aa[4] = {pa.x, pa.y, pa.z, pa.w};
            const float bb[4] = {vb.x, vb.y, vb.z, vb.w};
#pragma unroll
            for (int ii = 0; ii < 4; ii++)
#pragma unroll
                for (int jj = 0; jj < 4; jj++)
                    acc[ii][jj] = fmaf(aa[ii], bb[jj], acc[ii][jj]);
        }
    }

    // epilogue: normalize, write context as [B, S, D]
#pragma unroll
    for (int ii = 0; ii < 4; ii++) {
        const float inv = 1.0f / l[ii];
#pragma unroll
        for (int jj = 0; jj < 4; jj++)
            g_C[((size_t)b * SEQ + (qrow + ii)) * DMODEL + h * DHEAD + tx * 4 + jj] =
                acc[ii][jj] * inv;
    }
}

// ---------------------------------------------------------------------------
extern "C" void kernel_launch(void* const* d_in, const int* in_sizes, int n_in,
                              void* d_out, int out_size)
{
    (void)in_sizes; (void)n_in; (void)out_size;
    const float* query = (const float*)d_in[0];
    const float* key_  = (const float*)d_in[1];
    const float* value = (const float*)d_in[2];
    const int*   mask  = (const int*)  d_in[3];
    const float* group = (const float*)d_in[4];
    const float* Wq = (const float*)d_in[5];
    const float* bq = (const float*)d_in[6];
    const float* Wk = (const float*)d_in[7];
    const float* bk = (const float*)d_in[8];
    const float* Wv = (const float*)d_in[9];
    const float* bv = (const float*)d_in[10];
    const float* Wo = (const float*)d_in[11];
    const float* bo = (const float*)d_in[12];
    float* out = (float*)d_out;

    float *Qp, *Kp, *Vp, *Cp;
    cudaGetSymbolAddress((void**)&Qp, g_Q);
    cudaGetSymbolAddress((void**)&Kp, g_K);
    cudaGetSymbolAddress((void**)&Vp, g_V);
    cudaGetSymbolAddress((void**)&Cp, g_C);

    cudaFuncSetAttribute(attn_kernel,
                         cudaFuncAttributeMaxDynamicSharedMemorySize,
                         ATT_SMEM_BYTES);

    const dim3 gg(DMODEL / 128, NTOK / 128);  // (8, 32)
    sgemm_kernel<<<gg, 256>>>(query, Wq, bq, Qp, 1);
    sgemm_kernel<<<gg, 256>>>(key_,  Wk, bk, Kp, 1);
    sgemm_kernel<<<gg, 256>>>(value, Wv, bv, Vp, 1);

    attn_kernel<<<dim3(SEQ / 64, NHEAD, BATCH), 256, ATT_SMEM_BYTES>>>(mask, group);

    sgemm_kernel<<<gg, 256>>>(Cp, Wo, bo, out, 0);
}

// round 3
// speedup vs baseline: 1.4342x; 1.4342x over previous
#include <cuda_runtime.h>
#include <cuda_bf16.h>
#include <math.h>
#include <stdint.h>

#define BATCH  4
#define SEQ    1024
#define DMODEL 1024
#define NHEAD  16
#define DHEAD  64
#define NTOK   (BATCH * SEQ)

// ---------------- scratch (device globals; no runtime alloc) ----------------
__device__ float g_Q[NTOK * DMODEL];   // [B*S, D] plain row-major
__device__ float g_K[NTOK * DMODEL];
__device__ float g_V[NTOK * DMODEL];
__device__ float g_C[NTOK * DMODEL];

// bf16 hi/lo operands, plain row-major [rows][1024]
__device__ __nv_bfloat16 g_qh[NTOK * DMODEL], g_ql[NTOK * DMODEL];
__device__ __nv_bfloat16 g_kh[NTOK * DMODEL], g_kl[NTOK * DMODEL];
__device__ __nv_bfloat16 g_vh[NTOK * DMODEL], g_vl[NTOK * DMODEL];
__device__ __nv_bfloat16 g_ch[NTOK * DMODEL], g_cl[NTOK * DMODEL];
__device__ __nv_bfloat16 g_wqh[DMODEL * DMODEL], g_wql[DMODEL * DMODEL];
__device__ __nv_bfloat16 g_wkh[DMODEL * DMODEL], g_wkl[DMODEL * DMODEL];
__device__ __nv_bfloat16 g_wvh[DMODEL * DMODEL], g_wvl[DMODEL * DMODEL];
__device__ __nv_bfloat16 g_woh[DMODEL * DMODEL], g_wol[DMODEL * DMODEL];

// ---------------------------------------------------------------------------
// fp32 -> bf16 hi/lo split (plain row-major). One thread = 8 elements.
// ---------------------------------------------------------------------------
__global__ __launch_bounds__(256) void cvt_kernel(
    const float* __restrict__ src,
    __nv_bfloat16* __restrict__ hi, __nv_bfloat16* __restrict__ lo, int nrows)
{
    const int t = blockIdx.x * 256 + threadIdx.x;
    if (t >= nrows * (DMODEL / 8)) return;
    const int idx = t * 8;

    const float4 a = *(const float4*)(src + idx);
    const float4 b = *(const float4*)(src + idx + 4);
    const float f[8] = {a.x, a.y, a.z, a.w, b.x, b.y, b.z, b.w};

    union { __nv_bfloat16 h[8]; uint4 u; } ph, pl;
#pragma unroll
    for (int i = 0; i < 8; i++) {
        const __nv_bfloat16 hh = __float2bfloat16(f[i]);
        ph.h[i] = hh;
        pl.h[i] = __float2bfloat16(f[i] - __bfloat162float(hh));
    }
    *(uint4*)(hi + idx) = ph.u;
    *(uint4*)(lo + idx) = pl.u;
}

// ---------------------------------------------------------------------------
// bf16x3 GEMM via mma.sync (sm_80+ path; works on base sm_100 target):
// out[r, c] = sum_k A[r,k] * W[c,k] + bias[c]
// CTA 128x128, BK=32, 3-stage cp.async pipeline, 256 threads (8 warps 2x4).
// ---------------------------------------------------------------------------
#define BM 128
#define BN 128
#define BK 32
#define STAGES 3
#define KTILES (DMODEL / BK)          // 32
#define PAD_STRIDE 40                 // bf16 elems per smem row (80B)
#define TILE_B (128 * PAD_STRIDE * 2) // 10240 bytes per operand tile
#define STAGE_B (4 * TILE_B)          // Ah, Al, Bh, Bl
#define GEMM_SMEM (STAGES * STAGE_B)  // 122880

__device__ __forceinline__ uint32_t s2u(const void* p) {
    uint32_t a;
    asm("{ .reg .u64 t; cvta.to.shared.u64 t, %1; cvt.u32.u64 %0, t; }"
        : "=r"(a) : "l"(p));
    return a;
}
__device__ __forceinline__ void cp16(uint32_t dst, const void* src) {
    asm volatile("cp.async.cg.shared.global [%0], [%1], 16;"
                 :: "r"(dst), "l"(src));
}
__device__ __forceinline__ void ldm_x4(uint32_t* r, uint32_t addr) {
    asm volatile("ldmatrix.sync.aligned.m8n8.x4.shared.b16 {%0,%1,%2,%3}, [%4];"
                 : "=r"(r[0]), "=r"(r[1]), "=r"(r[2]), "=r"(r[3]) : "r"(addr));
}
__device__ __forceinline__ void mma_bf16(float* c, const uint32_t* a,
                                         const uint32_t* b) {
    asm volatile(
        "mma.sync.aligned.m16n8k16.row.col.f32.bf16.bf16.f32 "
        "{%0,%1,%2,%3}, {%4,%5,%6,%7}, {%8,%9}, {%0,%1,%2,%3};"
        : "+f"(c[0]), "+f"(c[1]), "+f"(c[2]), "+f"(c[3])
        : "r"(a[0]), "r"(a[1]), "r"(a[2]), "r"(a[3]), "r"(b[0]), "r"(b[1]));
}

__global__ __launch_bounds__(256, 1) void gemm_kernel(
    const __nv_bfloat16* __restrict__ aH, const __nv_bfloat16* __restrict__ aL,
    const __nv_bfloat16* __restrict__ bH, const __nv_bfloat16* __restrict__ bL,
    const float* __restrict__ bias, float* __restrict__ out)
{
    extern __shared__ __align__(16) char smem[];
    const uint32_t sb = s2u(smem);
    const int tid  = threadIdx.x;
    const int lane = tid & 31;
    const int wid  = tid >> 5;
    const int warpM = wid >> 2;         // 0..1
    const int warpN = wid & 3;          // 0..3
    const int brow  = blockIdx.y * BM;
    const int bcol  = blockIdx.x * BN;

    // per-thread cp.async mapping: 2 chunks of 16B per operand tile
    const int c0r = (tid * 2) >> 3;          // chunk pair: rows
    const int c0q = (tid * 2) & 7;           // 0,2,4,6 -> quad*? (chunk%4)*? careful

    float acc[4][4][4];
#pragma unroll
    for (int i = 0; i < 4; i++)
#pragma unroll
        for (int j = 0; j < 4; j++)
#pragma unroll
            for (int k = 0; k < 4; k++) acc[i][j][k] = 0.0f;

    auto load_stage = [&](int kb, int s) {
        const int k0 = kb * BK;
        const uint32_t base = sb + (uint32_t)s * STAGE_B;
#pragma unroll
        for (int i = 0; i < 2; i++) {
            const int c = tid + i * 256;       // 0..511
            const int r = c >> 2;              // row 0..127
            const int q = c & 3;               // 16B quad in 64B row
            const uint32_t dst = base + (uint32_t)r * (PAD_STRIDE * 2) + q * 16;
            const size_t aoff = (size_t)(brow + r) * DMODEL + k0 + q * 8;
            const size_t boff = (size_t)(bcol + r) * DMODEL + k0 + q * 8;
            cp16(dst,              aH + aoff);
            cp16(dst + TILE_B,     aL + aoff);
            cp16(dst + 2 * TILE_B, bH + boff);
            cp16(dst + 3 * TILE_B, bL + boff);
        }
        asm volatile("cp.async.commit_group;" ::: "memory");
    };

    // ldmatrix per-thread address components
    const int l8 = lane & 7, lg = lane >> 3;
    const int a_row_off = ((lg & 1) ? 8 : 0) + l8;   // within 16-row tile
    const int a_col_off = (lg & 2) ? 8 : 0;          // within 16-col k-step
    const int b_row_off = ((lg >> 1) ? 8 : 0) + l8;  // n within 16
    const int b_col_off = (lg & 1) ? 8 : 0;          // k within 16

    for (int s = 0; s < STAGES - 1; s++) load_stage(s, s);

    for (int kb = 0; kb < KTILES; kb++) {
        asm volatile("cp.async.wait_group %0;" :: "n"(STAGES - 2));
        __syncthreads();

        if (kb + STAGES - 1 < KTILES)
            load_stage(kb + STAGES - 1, (kb + STAGES - 1) % STAGES);
        else
            asm volatile("cp.async.commit_group;" ::: "memory");

        const uint32_t stg = sb + (uint32_t)(kb % STAGES) * STAGE_B;
#pragma unroll
        for (int ks = 0; ks < 2; ks++) {
            uint32_t ah[4][4], al[4][4], bh[4][2], bl[4][2];
#pragma unroll
            for (int mt = 0; mt < 4; mt++) {
                const int row = warpM * 64 + mt * 16 + a_row_off;
                const int col = ks * 16 + a_col_off;
                const uint32_t ad = stg + (uint32_t)row * (PAD_STRIDE * 2) + col * 2;
                ldm_x4(ah[mt], ad);
                ldm_x4(al[mt], ad + TILE_B);
            }
#pragma unroll
            for (int pt = 0; pt < 2; pt++) {
                const int n   = warpN * 32 + pt * 16 + b_row_off;
                const int col = ks * 16 + b_col_off;
                const uint32_t bd = stg + 2 * TILE_B +
                                    (uint32_t)n * (PAD_STRIDE * 2) + col * 2;
                uint32_t t[4];
                ldm_x4(t, bd);
                bh[pt * 2][0] = t[0]; bh[pt * 2][1] = t[1];
                bh[pt * 2 + 1][0] = t[2]; bh[pt * 2 + 1][1] = t[3];
                ldm_x4(t, bd + TILE_B);
                bl[pt * 2][0] = t[0]; bl[pt * 2][1] = t[1];
                bl[pt * 2 + 1][0] = t[2]; bl[pt * 2 + 1][1] = t[3];
            }
#pragma unroll
            for (int mt = 0; mt < 4; mt++)
#pragma unroll
                for (int nt = 0; nt < 4; nt++) {
                    mma_bf16(acc[mt][nt], ah[mt], bh[nt]);
                    mma_bf16(acc[mt][nt], ah[mt], bl[nt]);
                    mma_bf16(acc[mt][nt], al[mt], bh[nt]);
                }
        }
    }

    // epilogue
#pragma unroll
    for (int mt = 0; mt < 4; mt++) {
        const int row = brow + warpM * 64 + mt * 16 + (lane >> 2);
#pragma unroll
        for (int nt = 0; nt < 4; nt++) {
            const int col = bcol + warpN * 32 + nt * 8 + (lane & 3) * 2;
            const float b0 = bias[col], b1 = bias[col + 1];
            float2 v0 = {acc[mt][nt][0] + b0, acc[mt][nt][1] + b1};
            float2 v1 = {acc[mt][nt][2] + b0, acc[mt][nt][3] + b1};
            *(float2*)(out + (size_t)row * DMODEL + col) = v0;
            *(float2*)(out + (size_t)(row + 8) * DMODEL + col) = v1;
        }
    }
}

// ---------------------------------------------------------------------------
// Flash-style attention (unchanged; plain [B*S, D] Q/K/V layout).
// ---------------------------------------------------------------------------
#define TPAD 68
#define ATT_SMEM_BYTES (4 * 64 * TPAD * 4)

__global__ __launch_bounds__(256) void attn_kernel(
    const int* __restrict__ mask, const float* __restrict__ group)
{
    extern __shared__ float sm[];
    float* Qs = sm;
    float* Ks = sm + 64 * TPAD;
    float* Vs = sm + 2 * 64 * TPAD;
    float* Ps = sm + 3 * 64 * TPAD;

    const int tid = threadIdx.x;
    const int tx  = tid & 15;
    const int ty  = tid >> 4;
    const int b   = blockIdx.z;
    const int h   = blockIdx.y;
    const int q0  = blockIdx.x * 64;

    const float* Qg = g_Q + ((size_t)(b * SEQ + q0)) * DMODEL + h * DHEAD;

#pragma unroll
    for (int i = 0; i < 4; i++) {
        const int idx = tid * 4 + i;
        const int r   = idx >> 4;
        const int c4  = (idx & 15) * 4;
        const float4 q = *(const float4*)(Qg + (size_t)r * DMODEL + c4);
        Qs[(c4 + 0) * TPAD + r] = q.x;
        Qs[(c4 + 1) * TPAD + r] = q.y;
        Qs[(c4 + 2) * TPAD + r] = q.z;
        Qs[(c4 + 3) * TPAD + r] = q.w;
    }

    float m[4], l[4], acc[4][4];
#pragma unroll
    for (int i = 0; i < 4; i++) {
        m[i] = -INFINITY; l[i] = 0.0f;
#pragma unroll
        for (int j = 0; j < 4; j++) acc[i][j] = 0.0f;
    }

    const int qrow = q0 + ty * 4;

    for (int kt = 0; kt < SEQ / 64; kt++) {
        const int k0 = kt * 64;
        const float* Kg = g_K + ((size_t)(b * SEQ + k0)) * DMODEL + h * DHEAD;
        const float* Vg = g_V + ((size_t)(b * SEQ + k0)) * DMODEL + h * DHEAD;

        __syncthreads();
#pragma unroll
        for (int i = 0; i < 4; i++) {
            const int idx = tid * 4 + i;
            const int r   = idx >> 4;
            const int c4  = (idx & 15) * 4;
            const float4 kv = *(const float4*)(Kg + (size_t)r * DMODEL + c4);
            Ks[(c4 + 0) * TPAD + r] = kv.x;
            Ks[(c4 + 1) * TPAD + r] = kv.y;
            Ks[(c4 + 2) * TPAD + r] = kv.z;
            Ks[(c4 + 3) * TPAD + r] = kv.w;
            const float4 vv = *(const float4*)(Vg + (size_t)r * DMODEL + c4);
            *(float4*)&Vs[r * TPAD + c4] = vv;
        }
        __syncthreads();

        float s[4][4];
#pragma unroll
        for (int i = 0; i < 4; i++)
#pragma unroll
            for (int j = 0; j < 4; j++) s[i][j] = 0.0f;

#pragma unroll 8
        for (int k = 0; k < DHEAD; k++) {
            const float4 qa = *(const float4*)&Qs[k * TPAD + ty * 4];
            const float4 kb = *(const float4*)&Ks[k * TPAD + tx * 4];
            const float aa[4] = {qa.x, qa.y, qa.z, qa.w};
            const float bb[4] = {kb.x, kb.y, kb.z, kb.w};
#pragma unroll
            for (int i = 0; i < 4; i++)
#pragma unroll
                for (int j = 0; j < 4; j++)
                    s[i][j] = fmaf(aa[i], bb[j], s[i][j]);
        }

        float g[4][4];
        const int kcol0 = k0 + tx * 4;
#pragma unroll
        for (int ii = 0; ii < 4; ii++) {
            const int q = qrow + ii;
            const size_t base = ((size_t)b * SEQ + q) * SEQ + kcol0;
            const int4   mk = *(const int4*)(mask + base);
            const float4 g4 = *(const float4*)(group + base);
            s[ii][0] = (mk.x || (q == kcol0 + 0)) ? s[ii][0] * 0.125f : -1e9f;
            s[ii][1] = (mk.y || (q == kcol0 + 1)) ? s[ii][1] * 0.125f : -1e9f;
            s[ii][2] = (mk.z || (q == kcol0 + 2)) ? s[ii][2] * 0.125f : -1e9f;
            s[ii][3] = (mk.w || (q == kcol0 + 3)) ? s[ii][3] * 0.125f : -1e9f;
            g[ii][0] = g4.x; g[ii][1] = g4.y; g[ii][2] = g4.z; g[ii][3] = g4.w;
        }

        float p[4][4];
#pragma unroll
        for (int ii = 0; ii < 4; ii++) {
            float rm = fmaxf(fmaxf(s[ii][0], s[ii][1]), fmaxf(s[ii][2], s[ii][3]));
#pragma unroll
            for (int off = 8; off >= 1; off >>= 1)
                rm = fmaxf(rm, __shfl_xor_sync(0xffffffffu, rm, off, 16));
            const float mn = fmaxf(m[ii], rm);
            float rs = 0.0f;
#pragma unroll
            for (int jj = 0; jj < 4; jj++) {
                p[ii][jj] = __expf(s[ii][jj] - mn);
                rs += p[ii][jj];
            }
#pragma unroll
            for (int off = 8; off >= 1; off >>= 1)
                rs += __shfl_xor_sync(0xffffffffu, rs, off, 16);
            const float sc = __expf(m[ii] - mn);
            l[ii] = l[ii] * sc + rs;
            m[ii] = mn;
#pragma unroll
            for (int jj = 0; jj < 4; jj++) acc[ii][jj] *= sc;
        }

#pragma unroll
        for (int ii = 0; ii < 4; ii++)
#pragma unroll
            for (int jj = 0; jj < 4; jj++)
                Ps[(tx * 4 + jj) * TPAD + ty * 4 + ii] = p[ii][jj] * g[ii][jj];
        __syncthreads();

#pragma unroll 8
        for (int i = 0; i < 64; i++) {
            const float4 pa = *(const float4*)&Ps[i * TPAD + ty * 4];
            const float4 vb = *(const float4*)&Vs[i * TPAD + tx * 4];
            const float aa[4] = {pa.x, pa.y, pa.z, pa.w};
            const float bb[4] = {vb.x, vb.y, vb.z, vb.w};
#pragma unroll
            for (int ii = 0; ii < 4; ii++)
#pragma unroll
                for (int jj = 0; jj < 4; jj++)
                    acc[ii][jj] = fmaf(aa[ii], bb[jj], acc[ii][jj]);
        }
    }

#pragma unroll
    for (int ii = 0; ii < 4; ii++) {
        const float inv = 1.0f / l[ii];
#pragma unroll
        for (int jj = 0; jj < 4; jj++)
            g_C[((size_t)b * SEQ + (qrow + ii)) * DMODEL + h * DHEAD + tx * 4 + jj] =
                acc[ii][jj] * inv;
    }
}

// ---------------------------------------------------------------------------
extern "C" void kernel_launch(void* const* d_in, const int* in_sizes, int n_in,
                              void* d_out, int out_size)
{
    (void)in_sizes; (void)n_in; (void)out_size;
    const float* query = (const float*)d_in[0];
    const float* key_  = (const float*)d_in[1];
    const float* value = (const float*)d_in[2];
    const int*   mask  = (const int*)  d_in[3];
    const float* group = (const float*)d_in[4];
    const float* Wq = (const float*)d_in[5];
    const float* bq = (const float*)d_in[6];
    const float* Wk = (const float*)d_in[7];
    const float* bk = (const float*)d_in[8];
    const float* Wv = (const float*)d_in[9];
    const float* bv = (const float*)d_in[10];
    const float* Wo = (const float*)d_in[11];
    const float* bo = (const float*)d_in[12];
    float* out = (float*)d_out;

    float *Qp, *Kp, *Vp, *Cp;
    cudaGetSymbolAddress((void**)&Qp, g_Q);
    cudaGetSymbolAddress((void**)&Kp, g_K);
    cudaGetSymbolAddress((void**)&Vp, g_V);
    cudaGetSymbolAddress((void**)&Cp, g_C);

    __nv_bfloat16 *qh, *ql, *kh, *kl, *vh, *vl, *ch, *cl;
    __nv_bfloat16 *wqh, *wql, *wkh, *wkl, *wvh, *wvl, *woh, *wol;
    cudaGetSymbolAddress((void**)&qh, g_qh);   cudaGetSymbolAddress((void**)&ql, g_ql);
    cudaGetSymbolAddress((void**)&kh, g_kh);   cudaGetSymbolAddress((void**)&kl, g_kl);
    cudaGetSymbolAddress((void**)&vh, g_vh);   cudaGetSymbolAddress((void**)&vl, g_vl);
    cudaGetSymbolAddress((void**)&ch, g_ch);   cudaGetSymbolAddress((void**)&cl, g_cl);
    cudaGetSymbolAddress((void**)&wqh, g_wqh); cudaGetSymbolAddress((void**)&wql, g_wql);
    cudaGetSymbolAddress((void**)&wkh, g_wkh); cudaGetSymbolAddress((void**)&wkl, g_wkl);
    cudaGetSymbolAddress((void**)&wvh, g_wvh); cudaGetSymbolAddress((void**)&wvl, g_wvl);
    cudaGetSymbolAddress((void**)&woh, g_woh); cudaGetSymbolAddress((void**)&wol, g_wol);

    cudaFuncSetAttribute(attn_kernel, cudaFuncAttributeMaxDynamicSharedMemorySize,
                         ATT_SMEM_BYTES);
    cudaFuncSetAttribute(gemm_kernel, cudaFuncAttributeMaxDynamicSharedMemorySize,
                         GEMM_SMEM);

    const int actBlocks = NTOK / 2;
    const int wBlocks   = DMODEL / 2;

    cvt_kernel<<<actBlocks, 256>>>(query, qh, ql, NTOK);
    cvt_kernel<<<actBlocks, 256>>>(key_,  kh, kl, NTOK);
    cvt_kernel<<<actBlocks, 256>>>(value, vh, vl, NTOK);
    cvt_kernel<<<wBlocks, 256>>>(Wq, wqh, wql, DMODEL);
    cvt_kernel<<<wBlocks, 256>>>(Wk, wkh, wkl, DMODEL);
    cvt_kernel<<<wBlocks, 256>>>(Wv, wvh, wvl, DMODEL);
    cvt_kernel<<<wBlocks, 256>>>(Wo, woh, wol, DMODEL);

    const dim3 gg(DMODEL / BN, NTOK / BM);  // (8, 32)
    gemm_kernel<<<gg, 256, GEMM_SMEM>>>(qh, ql, wqh, wql, bq, Qp);
    gemm_kernel<<<gg, 256, GEMM_SMEM>>>(kh, kl, wkh, wkl, bk, Kp);
    gemm_kernel<<<gg, 256, GEMM_SMEM>>>(vh, vl, wvh, wvl, bv, Vp);

    attn_kernel<<<dim3(SEQ / 64, NHEAD, BATCH), 256, ATT_SMEM_BYTES>>>(mask, group);

    cvt_kernel<<<actBlocks, 256>>>(Cp, ch, cl, NTOK);
    gemm_kernel<<<gg, 256, GEMM_SMEM>>>(ch, cl, woh, wol, bo, out);
}

// round 4
// speedup vs baseline: 2.5418x; 1.7722x over previous
#include <cuda_runtime.h>
#include <cuda_bf16.h>
#include <math.h>
#include <stdint.h>

#define BATCH  4
#define SEQ    1024
#define DMODEL 1024
#define NHEAD  16
#define DHEAD  64
#define NTOK   (BATCH * SEQ)

// ---------------- scratch (device globals; no runtime alloc) ----------------
// input-side bf16 hi/lo (row-major [rows][1024])
__device__ __nv_bfloat16 g_qh[NTOK * DMODEL], g_ql[NTOK * DMODEL];
__device__ __nv_bfloat16 g_kh[NTOK * DMODEL], g_kl[NTOK * DMODEL];
__device__ __nv_bfloat16 g_vh[NTOK * DMODEL], g_vl[NTOK * DMODEL];
__device__ __nv_bfloat16 g_wqh[DMODEL * DMODEL], g_wql[DMODEL * DMODEL];
__device__ __nv_bfloat16 g_wkh[DMODEL * DMODEL], g_wkl[DMODEL * DMODEL];
__device__ __nv_bfloat16 g_wvh[DMODEL * DMODEL], g_wvl[DMODEL * DMODEL];
__device__ __nv_bfloat16 g_woh[DMODEL * DMODEL], g_wol[DMODEL * DMODEL];
// projected Q/K/V hi/lo in [b,h,s,64] layout
__device__ __nv_bfloat16 g_oqh[NTOK * DMODEL], g_oql[NTOK * DMODEL];
__device__ __nv_bfloat16 g_okh[NTOK * DMODEL], g_okl[NTOK * DMODEL];
__device__ __nv_bfloat16 g_ovh[NTOK * DMODEL], g_ovl[NTOK * DMODEL];
// attention context hi/lo, row-major [tok][1024]
__device__ __nv_bfloat16 g_ch[NTOK * DMODEL], g_cl[NTOK * DMODEL];
// fused mask*group: allowed ? group : -1
__device__ float g_gm[BATCH * SEQ * SEQ];

// ---------------------------------------------------------------------------
__global__ __launch_bounds__(256) void cvt_kernel(
    const float* __restrict__ src,
    __nv_bfloat16* __restrict__ hi, __nv_bfloat16* __restrict__ lo, int nrows)
{
    const int t = blockIdx.x * 256 + threadIdx.x;
    if (t >= nrows * (DMODEL / 8)) return;
    const int idx = t * 8;
    const float4 a = *(const float4*)(src + idx);
    const float4 b = *(const float4*)(src + idx + 4);
    const float f[8] = {a.x, a.y, a.z, a.w, b.x, b.y, b.z, b.w};
    union { __nv_bfloat16 h[8]; uint4 u; } ph, pl;
#pragma unroll
    for (int i = 0; i < 8; i++) {
        const __nv_bfloat16 hh = __float2bfloat16(f[i]);
        ph.h[i] = hh;
        pl.h[i] = __float2bfloat16(f[i] - __bfloat162float(hh));
    }
    *(uint4*)(hi + idx) = ph.u;
    *(uint4*)(lo + idx) = pl.u;
}

// gm = (mask || q==k) ? group : -1
__global__ __launch_bounds__(256) void prep_gm_kernel(
    const int* __restrict__ mask, const float* __restrict__ group,
    float* __restrict__ gm)
{
    const int t = blockIdx.x * 256 + threadIdx.x;
    if (t >= BATCH * SEQ * SEQ / 4) return;
    const int i = t * 4;
    const int q = (i >> 10) & 1023;
    const int k = i & 1023;
    const int4   mk = *(const int4*)(mask + i);
    const float4 gr = *(const float4*)(group + i);
    float4 o;
    o.x = (mk.x || q == k + 0) ? gr.x : -1.0f;
    o.y = (mk.y || q == k + 1) ? gr.y : -1.0f;
    o.z = (mk.z || q == k + 2) ? gr.z : -1.0f;
    o.w = (mk.w || q == k + 3) ? gr.w : -1.0f;
    *(float4*)(gm + i) = o;
}

// ---------------------------------------------------------------------------
// shared PTX helpers
// ---------------------------------------------------------------------------
__device__ __forceinline__ uint32_t s2u(const void* p) {
    uint32_t a;
    asm("{ .reg .u64 t; cvta.to.shared.u64 t, %1; cvt.u32.u64 %0, t; }"
        : "=r"(a) : "l"(p));
    return a;
}
__device__ __forceinline__ void cp16(uint32_t dst, const void* src) {
    asm volatile("cp.async.cg.shared.global [%0], [%1], 16;" :: "r"(dst), "l"(src));
}
__device__ __forceinline__ void ldm_x4(uint32_t* r, uint32_t addr) {
    asm volatile("ldmatrix.sync.aligned.m8n8.x4.shared.b16 {%0,%1,%2,%3}, [%4];"
                 : "=r"(r[0]), "=r"(r[1]), "=r"(r[2]), "=r"(r[3]) : "r"(addr));
}
__device__ __forceinline__ void ldm_x4_t(uint32_t* r, uint32_t addr) {
    asm volatile("ldmatrix.sync.aligned.m8n8.x4.trans.shared.b16 {%0,%1,%2,%3}, [%4];"
                 : "=r"(r[0]), "=r"(r[1]), "=r"(r[2]), "=r"(r[3]) : "r"(addr));
}
__device__ __forceinline__ void mma_bf16(float* c, const uint32_t* a,
                                         const uint32_t* b) {
    asm volatile(
        "mma.sync.aligned.m16n8k16.row.col.f32.bf16.bf16.f32 "
        "{%0,%1,%2,%3}, {%4,%5,%6,%7}, {%8,%9}, {%0,%1,%2,%3};"
        : "+f"(c[0]), "+f"(c[1]), "+f"(c[2]), "+f"(c[3])
        : "r"(a[0]), "r"(a[1]), "r"(a[2]), "r"(a[3]), "r"(b[0]), "r"(b[1]));
}
__device__ __forceinline__ uint32_t swz(uint32_t byte) {
    return byte ^ ((byte >> 3) & 0x70);
}
// pack two fp32 into bf16x2 hi + residual-lo bf16x2
__device__ __forceinline__ void split2(float x, float y, uint32_t& hi, uint32_t& lo) {
    const __nv_bfloat16 hx = __float2bfloat16(x), hy = __float2bfloat16(y);
    const __nv_bfloat162 h(hx, hy);
    const __nv_bfloat162 l(__float2bfloat16(x - __bfloat162float(hx)),
                           __float2bfloat16(y - __bfloat162float(hy)));
    hi = *(const uint32_t*)&h;
    lo = *(const uint32_t*)&l;
}

// ---------------------------------------------------------------------------
// bf16x3 GEMM (mode 0: fp32 row-major out; mode 1: bf16 hi/lo [b,h,s,64] out)
// ---------------------------------------------------------------------------
#define BM 128
#define BN 128
#define BK 32
#define STAGES 3
#define KTILES (DMODEL / BK)
#define PAD_STRIDE 40
#define TILE_B (128 * PAD_STRIDE * 2)
#define STAGE_B (4 * TILE_B)
#define GEMM_SMEM (STAGES * STAGE_B)

__global__ __launch_bounds__(256, 1) void gemm_kernel(
    const __nv_bfloat16* __restrict__ aH, const __nv_bfloat16* __restrict__ aL,
    const __nv_bfloat16* __restrict__ bH, const __nv_bfloat16* __restrict__ bL,
    const float* __restrict__ bias, float* __restrict__ outF,
    __nv_bfloat16* __restrict__ outH, __nv_bfloat16* __restrict__ outL, int mode)
{
    extern __shared__ __align__(16) char smem[];
    const uint32_t sb = s2u(smem);
    const int tid  = threadIdx.x;
    const int lane = tid & 31;
    const int wid  = tid >> 5;
    const int warpM = wid >> 2;
    const int warpN = wid & 3;
    const int brow  = blockIdx.y * BM;
    const int bcol  = blockIdx.x * BN;

    float acc[4][4][4];
#pragma unroll
    for (int i = 0; i < 4; i++)
#pragma unroll
        for (int j = 0; j < 4; j++)
#pragma unroll
            for (int k = 0; k < 4; k++) acc[i][j][k] = 0.0f;

    auto load_stage = [&](int kb, int s) {
        const int k0 = kb * BK;
        const uint32_t base = sb + (uint32_t)s * STAGE_B;
#pragma unroll
        for (int i = 0; i < 2; i++) {
            const int c = tid + i * 256;
            const int r = c >> 2;
            const int q = c & 3;
            const uint32_t dst = base + (uint32_t)r * (PAD_STRIDE * 2) + q * 16;
            const size_t aoff = (size_t)(brow + r) * DMODEL + k0 + q * 8;
            const size_t boff = (size_t)(bcol + r) * DMODEL + k0 + q * 8;
            cp16(dst,              aH + aoff);
            cp16(dst + TILE_B,     aL + aoff);
            cp16(dst + 2 * TILE_B, bH + boff);
            cp16(dst + 3 * TILE_B, bL + boff);
        }
        asm volatile("cp.async.commit_group;" ::: "memory");
    };

    const int l8 = lane & 7, lg = lane >> 3;
    const int a_row_off = ((lg & 1) ? 8 : 0) + l8;
    const int a_col_off = (lg & 2) ? 8 : 0;
    const int b_row_off = ((lg >> 1) ? 8 : 0) + l8;
    const int b_col_off = (lg & 1) ? 8 : 0;

    for (int s = 0; s < STAGES - 1; s++) load_stage(s, s);

    for (int kb = 0; kb < KTILES; kb++) {
        asm volatile("cp.async.wait_group %0;" :: "n"(STAGES - 2));
        __syncthreads();
        if (kb + STAGES - 1 < KTILES)
            load_stage(kb + STAGES - 1, (kb + STAGES - 1) % STAGES);
        else
            asm volatile("cp.async.commit_group;" ::: "memory");

        const uint32_t stg = sb + (uint32_t)(kb % STAGES) * STAGE_B;
#pragma unroll
        for (int ks = 0; ks < 2; ks++) {
            uint32_t ah[4][4], al[4][4], bh[4][2], bl[4][2];
#pragma unroll
            for (int mt = 0; mt < 4; mt++) {
                const int row = warpM * 64 + mt * 16 + a_row_off;
                const int col = ks * 16 + a_col_off;
                const uint32_t ad = stg + (uint32_t)row * (PAD_STRIDE * 2) + col * 2;
                ldm_x4(ah[mt], ad);
                ldm_x4(al[mt], ad + TILE_B);
            }
#pragma unroll
            for (int pt = 0; pt < 2; pt++) {
                const int n   = warpN * 32 + pt * 16 + b_row_off;
                const int col = ks * 16 + b_col_off;
                const uint32_t bd = stg + 2 * TILE_B +
                                    (uint32_t)n * (PAD_STRIDE * 2) + col * 2;
                uint32_t t[4];
                ldm_x4(t, bd);
                bh[pt * 2][0] = t[0]; bh[pt * 2][1] = t[1];
                bh[pt * 2 + 1][0] = t[2]; bh[pt * 2 + 1][1] = t[3];
                ldm_x4(t, bd + TILE_B);
                bl[pt * 2][0] = t[0]; bl[pt * 2][1] = t[1];
                bl[pt * 2 + 1][0] = t[2]; bl[pt * 2 + 1][1] = t[3];
            }
#pragma unroll
            for (int mt = 0; mt < 4; mt++)
#pragma unroll
                for (int nt = 0; nt < 4; nt++) {
                    mma_bf16(acc[mt][nt], ah[mt], bh[nt]);
                    mma_bf16(acc[mt][nt], ah[mt], bl[nt]);
                    mma_bf16(acc[mt][nt], al[mt], bh[nt]);
                }
        }
    }

#pragma unroll
    for (int mt = 0; mt < 4; mt++) {
        const int row = brow + warpM * 64 + mt * 16 + (lane >> 2);
#pragma unroll
        for (int nt = 0; nt < 4; nt++) {
            const int col = bcol + warpN * 32 + nt * 8 + (lane & 3) * 2;
            const float b0 = bias[col], b1 = bias[col + 1];
            const float v00 = acc[mt][nt][0] + b0, v01 = acc[mt][nt][1] + b1;
            const float v10 = acc[mt][nt][2] + b0, v11 = acc[mt][nt][3] + b1;
            if (mode == 0) {
                *(float2*)(outF + (size_t)row * DMODEL + col) = make_float2(v00, v01);
                *(float2*)(outF + (size_t)(row + 8) * DMODEL + col) = make_float2(v10, v11);
            } else {
                const int h = col >> 6, dk = col & 63;
                const int bi = row >> 10, s = row & 1023;
                const size_t d0 = (((size_t)(bi * NHEAD + h)) * SEQ + s) * DHEAD + dk;
                uint32_t hi, lo;
                split2(v00, v01, hi, lo);
                *(uint32_t*)(outH + d0) = hi;
                *(uint32_t*)(outL + d0) = lo;
                split2(v10, v11, hi, lo);
                *(uint32_t*)(outH + d0 + 8 * DHEAD) = hi;
                *(uint32_t*)(outL + d0 + 8 * DHEAD) = lo;
            }
        }
    }
}

// ---------------------------------------------------------------------------
// Tensor-core flash attention. CTA = 128 q-rows x one (b,h). 8 warps x 16 rows.
// K-tiles of 64 keys, double-buffered cp.async. bf16x3 for QK^T and PV.
// smem: QH 16K | QL 16K | 2 stages x (KH|KL|VH|VL 8K each).
// ---------------------------------------------------------------------------
#define ATT_QH 0
#define ATT_QL 16384
#define ATT_STG0 32768
#define ATT_STG_B 32768
#define ATT_SMEM (32768 + 2 * ATT_STG_B)   // 98304

__global__ __launch_bounds__(256, 1) void attn_kernel(const float* __restrict__ gm)
{
    extern __shared__ __align__(16) char smem[];
    const uint32_t sb = s2u(smem);
    const int tid  = threadIdx.x;
    const int lane = tid & 31;
    const int w    = tid >> 5;
    const int h    = blockIdx.x;
    const int q0   = blockIdx.y * 128;
    const int b    = blockIdx.z;
    const int bh   = b * NHEAD + h;

    const __nv_bfloat16* Qh = g_oqh + ((size_t)bh * SEQ + q0) * DHEAD;
    const __nv_bfloat16* Ql = g_oql + ((size_t)bh * SEQ + q0) * DHEAD;
    const __nv_bfloat16* Kh = g_okh + (size_t)bh * SEQ * DHEAD;
    const __nv_bfloat16* Kl = g_okl + (size_t)bh * SEQ * DHEAD;
    const __nv_bfloat16* Vh = g_ovh + (size_t)bh * SEQ * DHEAD;
    const __nv_bfloat16* Vl = g_ovl + (size_t)bh * SEQ * DHEAD;

    // ---- prologue loads ----
    // Q (128 rows x 128B, hi+lo)
#pragma unroll
    for (int i = 0; i < 4; i++) {
        const int c = tid + i * 256;      // 0..1023
        const int r = c >> 3, off = c & 7;
        const uint32_t d = swz((uint32_t)r * 128 + off * 16);
        cp16(sb + ATT_QH + d, Qh + (size_t)r * DHEAD + off * 8);
        cp16(sb + ATT_QL + d, Ql + (size_t)r * DHEAD + off * 8);
    }
    auto load_stage = [&](int kt, int s) {
        const int k0 = kt * 64;
        const uint32_t base = sb + ATT_STG0 + (uint32_t)s * ATT_STG_B;
#pragma unroll
        for (int i = 0; i < 2; i++) {
            const int c = tid + i * 256;  // 0..511
            const int r = c >> 3, off = c & 7;
            const uint32_t d = swz((uint32_t)r * 128 + off * 16);
            const size_t g = (size_t)(k0 + r) * DHEAD + off * 8;
            cp16(base + d,         Kh + g);
            cp16(base + 8192 + d,  Kl + g);
            cp16(base + 16384 + d, Vh + g);
            cp16(base + 24576 + d, Vl + g);
        }
    };
    load_stage(0, 0);
    asm volatile("cp.async.commit_group;" ::: "memory");  // group: Q + stage0
    load_stage(1, 1);
    asm volatile("cp.async.commit_group;" ::: "memory");
    asm volatile("cp.async.wait_group 1;" ::: "memory");
    __syncthreads();

    const int l8 = lane & 7, lg = lane >> 3;
    const int a_row_off = ((lg & 1) ? 8 : 0) + l8;
    const int a_col_off = (lg & 2) ? 8 : 0;
    const int b_row_off = ((lg >> 1) ? 8 : 0) + l8;
    const int b_col_off = (lg & 1) ? 8 : 0;

    // Q fragments: [ks 0..3][4 regs], hi+lo (resident all kernel)
    uint32_t qfh[4][4], qfl[4][4];
#pragma unroll
    for (int ks = 0; ks < 4; ks++) {
        const int row = w * 16 + a_row_off;
        const int col = ks * 16 + a_col_off;
        const uint32_t d = swz((uint32_t)row * 128 + col * 2);
        ldm_x4(qfh[ks], sb + ATT_QH + d);
        ldm_x4(qfl[ks], sb + ATT_QL + d);
    }

    float accv[8][4];
#pragma unroll
    for (int i = 0; i < 8; i++)
#pragma unroll
        for (int j = 0; j < 4; j++) accv[i][j] = 0.0f;
    float m0 = -INFINITY, m1 = -INFINITY, l0 = 0.0f, l1 = 0.0f;

    const int r0 = lane >> 2;                 // rows within warp 16-block
    const int qrow0 = q0 + w * 16 + r0;
    const float* gmRow0 = gm + ((size_t)b * SEQ + qrow0) * SEQ;
    const float* gmRow1 = gmRow0 + 8 * SEQ;
    const int colq = (lane & 3) * 2;

    for (int kt = 0; kt < SEQ / 64; kt++) {
        const int st = kt & 1;
        const uint32_t stg = sb + ATT_STG0 + (uint32_t)st * ATT_STG_B;

        // ---- S = Q K^T (bf16x3) ----
        float s[8][4];
#pragma unroll
        for (int i = 0; i < 8; i++)
#pragma unroll
            for (int j = 0; j < 4; j++) s[i][j] = 0.0f;
#pragma unroll
        for (int g16 = 0; g16 < 4; g16++) {
#pragma unroll
            for (int ks = 0; ks < 4; ks++) {
                const int row = g16 * 16 + b_row_off;
                const int col = ks * 16 + b_col_off;
                const uint32_t d = swz((uint32_t)row * 128 + col * 2);
                uint32_t kh4[4], kl4[4];
                ldm_x4(kh4, stg + d);
                ldm_x4(kl4, stg + 8192 + d);
                uint32_t bh0[2] = {kh4[0], kh4[1]}, bh1[2] = {kh4[2], kh4[3]};
                uint32_t bl0[2] = {kl4[0], kl4[1]}, bl1[2] = {kl4[2], kl4[3]};
                mma_bf16(s[g16 * 2],     qfh[ks], bh0);
                mma_bf16(s[g16 * 2],     qfh[ks], bl0);
                mma_bf16(s[g16 * 2],     qfl[ks], bh0);
                mma_bf16(s[g16 * 2 + 1], qfh[ks], bh1);
                mma_bf16(s[g16 * 2 + 1], qfh[ks], bl1);
                mma_bf16(s[g16 * 2 + 1], qfl[ks], bh1);
            }
        }

        // ---- online softmax + group weighting ----
        float rm0 = -INFINITY, rm1 = -INFINITY;
#pragma unroll
        for (int nt = 0; nt < 8; nt++) {
            s[nt][0] *= 0.125f; s[nt][1] *= 0.125f;
            s[nt][2] *= 0.125f; s[nt][3] *= 0.125f;
            rm0 = fmaxf(rm0, fmaxf(s[nt][0], s[nt][1]));
            rm1 = fmaxf(rm1, fmaxf(s[nt][2], s[nt][3]));
        }
        rm0 = fmaxf(rm0, __shfl_xor_sync(0xffffffffu, rm0, 1));
        rm0 = fmaxf(rm0, __shfl_xor_sync(0xffffffffu, rm0, 2));
        rm1 = fmaxf(rm1, __shfl_xor_sync(0xffffffffu, rm1, 1));
        rm1 = fmaxf(rm1, __shfl_xor_sync(0xffffffffu, rm1, 2));
        const float m0n = fmaxf(m0, rm0);
        const float m1n = fmaxf(m1, rm1);
        const float c0 = __expf(m0 - m0n);
        const float c1 = __expf(m1 - m1n);
        l0 *= c0; l1 *= c1;
        m0 = m0n; m1 = m1n;
#pragma unroll
        for (int nt = 0; nt < 8; nt++) {
            accv[nt][0] *= c0; accv[nt][1] *= c0;
            accv[nt][2] *= c1; accv[nt][3] *= c1;
        }

        uint32_t aPh[4][4], aPl[4][4];
        const int kbase = kt * 64 + colq;
#pragma unroll
        for (int nt = 0; nt < 8; nt++) {
            const int kc = kbase + nt * 8;
            const float2 g0 = *(const float2*)(gmRow0 + kc);
            const float2 g1 = *(const float2*)(gmRow1 + kc);
            const float p00 = __expf(s[nt][0] - m0);
            const float p01 = __expf(s[nt][1] - m0);
            const float p10 = __expf(s[nt][2] - m1);
            const float p11 = __expf(s[nt][3] - m1);
            l0 += (g0.x >= 0.0f ? p00 : 0.0f) + (g0.y >= 0.0f ? p01 : 0.0f);
            l1 += (g1.x >= 0.0f ? p10 : 0.0f) + (g1.y >= 0.0f ? p11 : 0.0f);
            const float w00 = p00 * fmaxf(g0.x, 0.0f);
            const float w01 = p01 * fmaxf(g0.y, 0.0f);
            const float w10 = p10 * fmaxf(g1.x, 0.0f);
            const float w11 = p11 * fmaxf(g1.y, 0.0f);
            const int ks = nt >> 1, half = (nt & 1) * 2;
            split2(w00, w01, aPh[ks][half + 0], aPl[ks][half + 0]);
            split2(w10, w11, aPh[ks][half + 1], aPl[ks][half + 1]);
        }

        // ---- acc += P V (bf16x3, V via ldmatrix.trans) ----
#pragma unroll
        for (int ks = 0; ks < 4; ks++) {
#pragma unroll
            for (int ng = 0; ng < 4; ng++) {
                const int row = ks * 16 + ((lg & 1) ? 8 : 0) + l8;
                const int col = ng * 16 + ((lg >> 1) ? 8 : 0);
                const uint32_t d = swz((uint32_t)row * 128 + col * 2);
                uint32_t vh4[4], vl4[4];
                ldm_x4_t(vh4, stg + 16384 + d);
                ldm_x4_t(vl4, stg + 24576 + d);
                uint32_t bh0[2] = {vh4[0], vh4[1]}, bh1[2] = {vh4[2], vh4[3]};
                uint32_t bl0[2] = {vl4[0], vl4[1]}, bl1[2] = {vl4[2], vl4[3]};
                mma_bf16(accv[ng * 2],     aPh[ks], bh0);
                mma_bf16(accv[ng * 2],     aPh[ks], bl0);
                mma_bf16(accv[ng * 2],     aPl[ks], bh0);
                mma_bf16(accv[ng * 2 + 1], aPh[ks], bh1);
                mma_bf16(accv[ng * 2 + 1], aPh[ks], bl1);
                mma_bf16(accv[ng * 2 + 1], aPl[ks], bh1);
            }
        }

        // ---- pipeline advance ----
        __syncthreads();
        if (kt + 2 < SEQ / 64) load_stage(kt + 2, st);
        asm volatile("cp.async.commit_group;" ::: "memory");
        if (kt + 1 < SEQ / 64) {
            asm volatile("cp.async.wait_group 1;" ::: "memory");
            __syncthreads();
        }
    }

    // ---- epilogue: reduce l across quad, normalize, write C hi/lo ----
    l0 += __shfl_xor_sync(0xffffffffu, l0, 1);
    l0 += __shfl_xor_sync(0xffffffffu, l0, 2);
    l1 += __shfl_xor_sync(0xffffffffu, l1, 1);
    l1 += __shfl_xor_sync(0xffffffffu, l1, 2);
    const float inv0 = 1.0f / l0, inv1 = 1.0f / l1;

    const size_t tok0 = (size_t)b * SEQ + qrow0;
    __nv_bfloat16* ch0 = g_ch + tok0 * DMODEL + h * DHEAD + colq;
    __nv_bfloat16* cl0 = g_cl + tok0 * DMODEL + h * DHEAD + colq;
#pragma unroll
    for (int nt = 0; nt < 8; nt++) {
        uint32_t hi, lo;
        split2(accv[nt][0] * inv0, accv[nt][1] * inv0, hi, lo);
        *(uint32_t*)(ch0 + nt * 8) = hi;
        *(uint32_t*)(cl0 + nt * 8) = lo;
        split2(accv[nt][2] * inv1, accv[nt][3] * inv1, hi, lo);
        *(uint32_t*)(ch0 + 8 * DMODEL + nt * 8) = hi;
        *(uint32_t*)(cl0 + 8 * DMODEL + nt * 8) = lo;
    }
}

// ---------------------------------------------------------------------------
extern "C" void kernel_launch(void* const* d_in, const int* in_sizes, int n_in,
                              void* d_out, int out_size)
{
    (void)in_sizes; (void)n_in; (void)out_size;
    const float* query = (const float*)d_in[0];
    const float* key_  = (const float*)d_in[1];
    const float* value = (const float*)d_in[2];
    const int*   mask  = (const int*)  d_in[3];
    const float* group = (const float*)d_in[4];
    const float* Wq = (const float*)d_in[5];
    const float* bq = (const float*)d_in[6];
    const float* Wk = (const float*)d_in[7];
    const float* bk = (const float*)d_in[8];
    const float* Wv = (const float*)d_in[9];
    const float* bv = (const float*)d_in[10];
    const float* Wo = (const float*)d_in[11];
    const float* bo = (const float*)d_in[12];
    float* out = (float*)d_out;

    __nv_bfloat16 *qh, *ql, *kh, *kl, *vh, *vl, *ch, *cl;
    __nv_bfloat16 *wqh, *wql, *wkh, *wkl, *wvh, *wvl, *woh, *wol;
    __nv_bfloat16 *oqh, *oql, *okh, *okl, *ovh, *ovl;
    float* gmp;
    cudaGetSymbolAddress((void**)&qh, g_qh);   cudaGetSymbolAddress((void**)&ql, g_ql);
    cudaGetSymbolAddress((void**)&kh, g_kh);   cudaGetSymbolAddress((void**)&kl, g_kl);
    cudaGetSymbolAddress((void**)&vh, g_vh);   cudaGetSymbolAddress((void**)&vl, g_vl);
    cudaGetSymbolAddress((void**)&ch, g_ch);   cudaGetSymbolAddress((void**)&cl, g_cl);
    cudaGetSymbolAddress((void**)&wqh, g_wqh); cudaGetSymbolAddress((void**)&wql, g_wql);
    cudaGetSymbolAddress((void**)&wkh, g_wkh); cudaGetSymbolAddress((void**)&wkl, g_wkl);
    cudaGetSymbolAddress((void**)&wvh, g_wvh); cudaGetSymbolAddress((void**)&wvl, g_wvl);
    cudaGetSymbolAddress((void**)&woh, g_woh); cudaGetSymbolAddress((void**)&wol, g_wol);
    cudaGetSymbolAddress((void**)&oqh, g_oqh); cudaGetSymbolAddress((void**)&oql, g_oql);
    cudaGetSymbolAddress((void**)&okh, g_okh); cudaGetSymbolAddress((void**)&okl, g_okl);
    cudaGetSymbolAddress((void**)&ovh, g_ovh); cudaGetSymbolAddress((void**)&ovl, g_ovl);
    cudaGetSymbolAddress((void**)&gmp, g_gm);

    cudaFuncSetAttribute(gemm_kernel, cudaFuncAttributeMaxDynamicSharedMemorySize,
                         GEMM_SMEM);
    cudaFuncSetAttribute(attn_kernel, cudaFuncAttributeMaxDynamicSharedMemorySize,
                         ATT_SMEM);

    const int actBlocks = NTOK / 2;
    const int wBlocks   = DMODEL / 2;

    cvt_kernel<<<actBlocks, 256>>>(query, qh, ql, NTOK);
    cvt_kernel<<<actBlocks, 256>>>(key_,  kh, kl, NTOK);
    cvt_kernel<<<actBlocks, 256>>>(value, vh, vl, NTOK);
    cvt_kernel<<<wBlocks, 256>>>(Wq, wqh, wql, DMODEL);
    cvt_kernel<<<wBlocks, 256>>>(Wk, wkh, wkl, DMODEL);
    cvt_kernel<<<wBlocks, 256>>>(Wv, wvh, wvl, DMODEL);
    cvt_kernel<<<wBlocks, 256>>>(Wo, woh, wol, DMODEL);
    prep_gm_kernel<<<BATCH * SEQ * SEQ / 4 / 256, 256>>>(mask, group, gmp);

    const dim3 gg(DMODEL / BN, NTOK / BM);
    gemm_kernel<<<gg, 256, GEMM_SMEM>>>(qh, ql, wqh, wql, bq, nullptr, oqh, oql, 1);
    gemm_kernel<<<gg, 256, GEMM_SMEM>>>(kh, kl, wkh, wkl, bk, nullptr, okh, okl, 1);
    gemm_kernel<<<gg, 256, GEMM_SMEM>>>(vh, vl, wvh, wvl, bv, nullptr, ovh, ovl, 1);

    attn_kernel<<<dim3(NHEAD, SEQ / 128, BATCH), 256, ATT_SMEM>>>(gmp);

    gemm_kernel<<<gg, 256, GEMM_SMEM>>>(ch, cl, woh, wol, bo, out, nullptr, nullptr, 0);
}

// round 5
// speedup vs baseline: 2.6386x; 1.0381x over previous
#include <cuda_runtime.h>
#include <cuda_bf16.h>
#include <math.h>
#include <stdint.h>

#define BATCH  4
#define SEQ    1024
#define DMODEL 1024
#define NHEAD  16
#define DHEAD  64
#define NTOK   (BATCH * SEQ)

// ---------------- scratch (device globals; no runtime alloc) ----------------
__device__ __nv_bfloat16 g_qh[NTOK * DMODEL], g_ql[NTOK * DMODEL];
__device__ __nv_bfloat16 g_kh[NTOK * DMODEL], g_kl[NTOK * DMODEL];
__device__ __nv_bfloat16 g_vh[NTOK * DMODEL], g_vl[NTOK * DMODEL];
__device__ __nv_bfloat16 g_wqh[DMODEL * DMODEL], g_wql[DMODEL * DMODEL];
__device__ __nv_bfloat16 g_wkh[DMODEL * DMODEL], g_wkl[DMODEL * DMODEL];
__device__ __nv_bfloat16 g_wvh[DMODEL * DMODEL], g_wvl[DMODEL * DMODEL];
__device__ __nv_bfloat16 g_woh[DMODEL * DMODEL], g_wol[DMODEL * DMODEL];
// projected Q/K/V hi/lo in [b,h,s,64] layout  (Q pre-scaled by 0.125*log2e)
__device__ __nv_bfloat16 g_oqh[NTOK * DMODEL], g_oql[NTOK * DMODEL];
__device__ __nv_bfloat16 g_okh[NTOK * DMODEL], g_okl[NTOK * DMODEL];
__device__ __nv_bfloat16 g_ovh[NTOK * DMODEL], g_ovl[NTOK * DMODEL];
// attention context hi/lo, row-major [tok][1024]
__device__ __nv_bfloat16 g_ch[NTOK * DMODEL], g_cl[NTOK * DMODEL];
// fused mask*group: allowed ? group : -1
__device__ float g_gm[BATCH * SEQ * SEQ];

// ---------------------------------------------------------------------------
__global__ __launch_bounds__(256) void cvt_kernel(
    const float* __restrict__ src,
    __nv_bfloat16* __restrict__ hi, __nv_bfloat16* __restrict__ lo, int nrows)
{
    const int t = blockIdx.x * 256 + threadIdx.x;
    if (t >= nrows * (DMODEL / 8)) return;
    const int idx = t * 8;
    const float4 a = *(const float4*)(src + idx);
    const float4 b = *(const float4*)(src + idx + 4);
    const float f[8] = {a.x, a.y, a.z, a.w, b.x, b.y, b.z, b.w};
    union { __nv_bfloat16 h[8]; uint4 u; } ph, pl;
#pragma unroll
    for (int i = 0; i < 8; i++) {
        const __nv_bfloat16 hh = __float2bfloat16(f[i]);
        ph.h[i] = hh;
        pl.h[i] = __float2bfloat16(f[i] - __bfloat162float(hh));
    }
    *(uint4*)(hi + idx) = ph.u;
    *(uint4*)(lo + idx) = pl.u;
}

// gm = (mask || q==k) ? group : -1
__global__ __launch_bounds__(256) void prep_gm_kernel(
    const int* __restrict__ mask, const float* __restrict__ group,
    float* __restrict__ gm)
{
    const int t = blockIdx.x * 256 + threadIdx.x;
    if (t >= BATCH * SEQ * SEQ / 4) return;
    const int i = t * 4;
    const int q = (i >> 10) & 1023;
    const int k = i & 1023;
    const int4   mk = *(const int4*)(mask + i);
    const float4 gr = *(const float4*)(group + i);
    float4 o;
    o.x = (mk.x || q == k + 0) ? gr.x : -1.0f;
    o.y = (mk.y || q == k + 1) ? gr.y : -1.0f;
    o.z = (mk.z || q == k + 2) ? gr.z : -1.0f;
    o.w = (mk.w || q == k + 3) ? gr.w : -1.0f;
    *(float4*)(gm + i) = o;
}

// ---------------------------------------------------------------------------
// shared PTX helpers
// ---------------------------------------------------------------------------
__device__ __forceinline__ uint32_t s2u(const void* p) {
    uint32_t a;
    asm("{ .reg .u64 t; cvta.to.shared.u64 t, %1; cvt.u32.u64 %0, t; }"
        : "=r"(a) : "l"(p));
    return a;
}
__device__ __forceinline__ void cp16(uint32_t dst, const void* src) {
    asm volatile("cp.async.cg.shared.global [%0], [%1], 16;" :: "r"(dst), "l"(src));
}
__device__ __forceinline__ void ldm_x4(uint32_t* r, uint32_t addr) {
    asm volatile("ldmatrix.sync.aligned.m8n8.x4.shared.b16 {%0,%1,%2,%3}, [%4];"
                 : "=r"(r[0]), "=r"(r[1]), "=r"(r[2]), "=r"(r[3]) : "r"(addr));
}
__device__ __forceinline__ void ldm_x4_t(uint32_t* r, uint32_t addr) {
    asm volatile("ldmatrix.sync.aligned.m8n8.x4.trans.shared.b16 {%0,%1,%2,%3}, [%4];"
                 : "=r"(r[0]), "=r"(r[1]), "=r"(r[2]), "=r"(r[3]) : "r"(addr));
}
__device__ __forceinline__ void mma_bf16(float* c, const uint32_t* a,
                                         const uint32_t* b) {
    asm volatile(
        "mma.sync.aligned.m16n8k16.row.col.f32.bf16.bf16.f32 "
        "{%0,%1,%2,%3}, {%4,%5,%6,%7}, {%8,%9}, {%0,%1,%2,%3};"
        : "+f"(c[0]), "+f"(c[1]), "+f"(c[2]), "+f"(c[3])
        : "r"(a[0]), "r"(a[1]), "r"(a[2]), "r"(a[3]), "r"(b[0]), "r"(b[1]));
}
__device__ __forceinline__ uint32_t swz(uint32_t byte) {
    return byte ^ ((byte >> 3) & 0x70);
}
// pack two fp32 -> bf16x2 hi (x in low half) + residual-lo bf16x2
__device__ __forceinline__ void split2(float x, float y, uint32_t& hi, uint32_t& lo) {
    asm("cvt.rn.bf16x2.f32 %0, %1, %2;" : "=r"(hi) : "f"(y), "f"(x));
    const float xr = x - __uint_as_float(hi << 16);
    const float yr = y - __uint_as_float(hi & 0xffff0000u);
    asm("cvt.rn.bf16x2.f32 %0, %1, %2;" : "=r"(lo) : "f"(yr), "f"(xr));
}
__device__ __forceinline__ float ex2(float x) {
    float r;
    asm("ex2.approx.f32 %0, %1;" : "=f"(r) : "f"(x));
    return r;
}

// ---------------------------------------------------------------------------
// bf16x3 GEMM (mode 0: fp32 row-major out; mode 1: bf16 hi/lo [b,h,s,64] out,
// output scaled by oscale)
// ---------------------------------------------------------------------------
#define BM 128
#define BN 128
#define BK 32
#define STAGES 3
#define KTILES (DMODEL / BK)
#define PAD_STRIDE 40
#define TILE_B (128 * PAD_STRIDE * 2)
#define STAGE_B (4 * TILE_B)
#define GEMM_SMEM (STAGES * STAGE_B)

__global__ __launch_bounds__(256, 1) void gemm_kernel(
    const __nv_bfloat16* __restrict__ aH, const __nv_bfloat16* __restrict__ aL,
    const __nv_bfloat16* __restrict__ bH, const __nv_bfloat16* __restrict__ bL,
    const float* __restrict__ bias, float* __restrict__ outF,
    __nv_bfloat16* __restrict__ outH, __nv_bfloat16* __restrict__ outL,
    int mode, float oscale)
{
    extern __shared__ __align__(16) char smem[];
    const uint32_t sb = s2u(smem);
    const int tid  = threadIdx.x;
    const int lane = tid & 31;
    const int wid  = tid >> 5;
    const int warpM = wid >> 2;
    const int warpN = wid & 3;
    const int brow  = blockIdx.y * BM;
    const int bcol  = blockIdx.x * BN;

    float acc[4][4][4];
#pragma unroll
    for (int i = 0; i < 4; i++)
#pragma unroll
        for (int j = 0; j < 4; j++)
#pragma unroll
            for (int k = 0; k < 4; k++) acc[i][j][k] = 0.0f;

    auto load_stage = [&](int kb, int s) {
        const int k0 = kb * BK;
        const uint32_t base = sb + (uint32_t)s * STAGE_B;
#pragma unroll
        for (int i = 0; i < 2; i++) {
            const int c = tid + i * 256;
            const int r = c >> 2;
            const int q = c & 3;
            const uint32_t dst = base + (uint32_t)r * (PAD_STRIDE * 2) + q * 16;
            const size_t aoff = (size_t)(brow + r) * DMODEL + k0 + q * 8;
            const size_t boff = (size_t)(bcol + r) * DMODEL + k0 + q * 8;
            cp16(dst,              aH + aoff);
            cp16(dst + TILE_B,     aL + aoff);
            cp16(dst + 2 * TILE_B, bH + boff);
            cp16(dst + 3 * TILE_B, bL + boff);
        }
        asm volatile("cp.async.commit_group;" ::: "memory");
    };

    const int l8 = lane & 7, lg = lane >> 3;
    const int a_row_off = ((lg & 1) ? 8 : 0) + l8;
    const int a_col_off = (lg & 2) ? 8 : 0;
    const int b_row_off = ((lg >> 1) ? 8 : 0) + l8;
    const int b_col_off = (lg & 1) ? 8 : 0;

    for (int s = 0; s < STAGES - 1; s++) load_stage(s, s);

    for (int kb = 0; kb < KTILES; kb++) {
        asm volatile("cp.async.wait_group %0;" :: "n"(STAGES - 2));
        __syncthreads();
        if (kb + STAGES - 1 < KTILES)
            load_stage(kb + STAGES - 1, (kb + STAGES - 1) % STAGES);
        else
            asm volatile("cp.async.commit_group;" ::: "memory");

        const uint32_t stg = sb + (uint32_t)(kb % STAGES) * STAGE_B;
#pragma unroll
        for (int ks = 0; ks < 2; ks++) {
            uint32_t ah[4][4], al[4][4], bh[4][2], bl[4][2];
#pragma unroll
            for (int mt = 0; mt < 4; mt++) {
                const int row = warpM * 64 + mt * 16 + a_row_off;
                const int col = ks * 16 + a_col_off;
                const uint32_t ad = stg + (uint32_t)row * (PAD_STRIDE * 2) + col * 2;
                ldm_x4(ah[mt], ad);
                ldm_x4(al[mt], ad + TILE_B);
            }
#pragma unroll
            for (int pt = 0; pt < 2; pt++) {
                const int n   = warpN * 32 + pt * 16 + b_row_off;
                const int col = ks * 16 + b_col_off;
                const uint32_t bd = stg + 2 * TILE_B +
                                    (uint32_t)n * (PAD_STRIDE * 2) + col * 2;
                uint32_t t[4];
                ldm_x4(t, bd);
                bh[pt * 2][0] = t[0]; bh[pt * 2][1] = t[1];
                bh[pt * 2 + 1][0] = t[2]; bh[pt * 2 + 1][1] = t[3];
                ldm_x4(t, bd + TILE_B);
                bl[pt * 2][0] = t[0]; bl[pt * 2][1] = t[1];
                bl[pt * 2 + 1][0] = t[2]; bl[pt * 2 + 1][1] = t[3];
            }
#pragma unroll
            for (int mt = 0; mt < 4; mt++)
#pragma unroll
                for (int nt = 0; nt < 4; nt++) {
                    mma_bf16(acc[mt][nt], ah[mt], bh[nt]);
                    mma_bf16(acc[mt][nt], ah[mt], bl[nt]);
                    mma_bf16(acc[mt][nt], al[mt], bh[nt]);
                }
        }
    }

#pragma unroll
    for (int mt = 0; mt < 4; mt++) {
        const int row = brow + warpM * 64 + mt * 16 + (lane >> 2);
#pragma unroll
        for (int nt = 0; nt < 4; nt++) {
            const int col = bcol + warpN * 32 + nt * 8 + (lane & 3) * 2;
            const float b0 = bias[col], b1 = bias[col + 1];
            const float v00 = acc[mt][nt][0] + b0, v01 = acc[mt][nt][1] + b1;
            const float v10 = acc[mt][nt][2] + b0, v11 = acc[mt][nt][3] + b1;
            if (mode == 0) {
                *(float2*)(outF + (size_t)row * DMODEL + col) = make_float2(v00, v01);
                *(float2*)(outF + (size_t)(row + 8) * DMODEL + col) = make_float2(v10, v11);
            } else {
                const int h = col >> 6, dk = col & 63;
                const int bi = row >> 10, s = row & 1023;
                const size_t d0 = (((size_t)(bi * NHEAD + h)) * SEQ + s) * DHEAD + dk;
                uint32_t hi, lo;
                split2(v00 * oscale, v01 * oscale, hi, lo);
                *(uint32_t*)(outH + d0) = hi;
                *(uint32_t*)(outL + d0) = lo;
                split2(v10 * oscale, v11 * oscale, hi, lo);
                *(uint32_t*)(outH + d0 + 8 * DHEAD) = hi;
                *(uint32_t*)(outL + d0 + 8 * DHEAD) = lo;
            }
        }
    }
}

// ---------------------------------------------------------------------------
// Tensor-core flash attention (log2-domain softmax; Q pre-scaled by .125*log2e)
// CTA = 128 q-rows x one (b,h); 8 warps x 16 rows; 64-key double-buffered tiles.
// __launch_bounds__(256,2): 2 CTAs/SM (2x96KB smem), <=128 regs.
// ---------------------------------------------------------------------------
#define ATT_QH 0
#define ATT_QL 16384
#define ATT_STG0 32768
#define ATT_STG_B 32768
#define ATT_SMEM (32768 + 2 * ATT_STG_B)   // 98304

__global__ __launch_bounds__(256, 2) void attn_kernel(const float* __restrict__ gm)
{
    extern __shared__ __align__(16) char smem[];
    const uint32_t sb = s2u(smem);
    const int tid  = threadIdx.x;
    const int lane = tid & 31;
    const int w    = tid >> 5;
    const int h    = blockIdx.x;
    const int q0   = blockIdx.y * 128;
    const int b    = blockIdx.z;
    const int bh   = b * NHEAD + h;

    const __nv_bfloat16* Qh = g_oqh + ((size_t)bh * SEQ + q0) * DHEAD;
    const __nv_bfloat16* Ql = g_oql + ((size_t)bh * SEQ + q0) * DHEAD;
    const __nv_bfloat16* Kh = g_okh + (size_t)bh * SEQ * DHEAD;
    const __nv_bfloat16* Kl = g_okl + (size_t)bh * SEQ * DHEAD;
    const __nv_bfloat16* Vh = g_ovh + (size_t)bh * SEQ * DHEAD;
    const __nv_bfloat16* Vl = g_ovl + (size_t)bh * SEQ * DHEAD;

#pragma unroll
    for (int i = 0; i < 4; i++) {
        const int c = tid + i * 256;
        const int r = c >> 3, off = c & 7;
        const uint32_t d = swz((uint32_t)r * 128 + off * 16);
        cp16(sb + ATT_QH + d, Qh + (size_t)r * DHEAD + off * 8);
        cp16(sb + ATT_QL + d, Ql + (size_t)r * DHEAD + off * 8);
    }
    auto load_stage = [&](int kt, int s) {
        const int k0 = kt * 64;
        const uint32_t base = sb + ATT_STG0 + (uint32_t)s * ATT_STG_B;
#pragma unroll
        for (int i = 0; i < 2; i++) {
            const int c = tid + i * 256;
            const int r = c >> 3, off = c & 7;
            const uint32_t d = swz((uint32_t)r * 128 + off * 16);
            const size_t g = (size_t)(k0 + r) * DHEAD + off * 8;
            cp16(base + d,         Kh + g);
            cp16(base + 8192 + d,  Kl + g);
            cp16(base + 16384 + d, Vh + g);
            cp16(base + 24576 + d, Vl + g);
        }
    };
    load_stage(0, 0);
    asm volatile("cp.async.commit_group;" ::: "memory");
    load_stage(1, 1);
    asm volatile("cp.async.commit_group;" ::: "memory");
    asm volatile("cp.async.wait_group 1;" ::: "memory");
    __syncthreads();

    const int l8 = lane & 7, lg = lane >> 3;
    const int a_row_off = ((lg & 1) ? 8 : 0) + l8;
    const int a_col_off = (lg & 2) ? 8 : 0;
    const int b_row_off = ((lg >> 1) ? 8 : 0) + l8;
    const int b_col_off = (lg & 1) ? 8 : 0;

    // Only Q-hi fragments stay register-resident; Q-lo reloaded per tile.
    uint32_t qfh[4][4];
    const uint32_t qrowbyte = (uint32_t)(w * 16 + a_row_off) * 128;
#pragma unroll
    for (int ks = 0; ks < 4; ks++) {
        const uint32_t d = swz(qrowbyte + (ks * 16 + a_col_off) * 2);
        ldm_x4(qfh[ks], sb + ATT_QH + d);
    }

    float accv[8][4];
#pragma unroll
    for (int i = 0; i < 8; i++)
#pragma unroll
        for (int j = 0; j < 4; j++) accv[i][j] = 0.0f;
    float m0 = -INFINITY, m1 = -INFINITY, l0 = 0.0f, l1 = 0.0f;

    const int r0 = lane >> 2;
    const int qrow0 = q0 + w * 16 + r0;
    const float* gmRow0 = gm + ((size_t)b * SEQ + qrow0) * SEQ;
    const float* gmRow1 = gmRow0 + 8 * SEQ;
    const int colq = (lane & 3) * 2;

    for (int kt = 0; kt < SEQ / 64; kt++) {
        const int st = kt & 1;
        const uint32_t stg = sb + ATT_STG0 + (uint32_t)st * ATT_STG_B;

        // ---- S = Q K^T (bf16x3), scores already in log2 units ----
        float s[8][4];
#pragma unroll
        for (int i = 0; i < 8; i++)
#pragma unroll
            for (int j = 0; j < 4; j++) s[i][j] = 0.0f;
#pragma unroll
        for (int ks = 0; ks < 4; ks++) {
            uint32_t qfl[4];
            ldm_x4(qfl, sb + ATT_QL + swz(qrowbyte + (ks * 16 + a_col_off) * 2));
#pragma unroll
            for (int g16 = 0; g16 < 4; g16++) {
                const int row = g16 * 16 + b_row_off;
                const int col = ks * 16 + b_col_off;
                const uint32_t d = swz((uint32_t)row * 128 + col * 2);
                uint32_t kh4[4], kl4[4];
                ldm_x4(kh4, stg + d);
                ldm_x4(kl4, stg + 8192 + d);
                uint32_t bh0[2] = {kh4[0], kh4[1]}, bh1[2] = {kh4[2], kh4[3]};
                uint32_t bl0[2] = {kl4[0], kl4[1]}, bl1[2] = {kl4[2], kl4[3]};
                mma_bf16(s[g16 * 2],     qfh[ks], bh0);
                mma_bf16(s[g16 * 2],     qfh[ks], bl0);
                mma_bf16(s[g16 * 2],     qfl,     bh0);
                mma_bf16(s[g16 * 2 + 1], qfh[ks], bh1);
                mma_bf16(s[g16 * 2 + 1], qfh[ks], bl1);
                mma_bf16(s[g16 * 2 + 1], qfl,     bh1);
            }
        }

        // ---- online softmax (log2 domain) + group weighting ----
        float rm0 = -INFINITY, rm1 = -INFINITY;
#pragma unroll
        for (int nt = 0; nt < 8; nt++) {
            rm0 = fmaxf(rm0, fmaxf(s[nt][0], s[nt][1]));
            rm1 = fmaxf(rm1, fmaxf(s[nt][2], s[nt][3]));
        }
        rm0 = fmaxf(rm0, __shfl_xor_sync(0xffffffffu, rm0, 1));
        rm0 = fmaxf(rm0, __shfl_xor_sync(0xffffffffu, rm0, 2));
        rm1 = fmaxf(rm1, __shfl_xor_sync(0xffffffffu, rm1, 1));
        rm1 = fmaxf(rm1, __shfl_xor_sync(0xffffffffu, rm1, 2));
        const float m0n = fmaxf(m0, rm0);
        const float m1n = fmaxf(m1, rm1);
        const float c0 = ex2(m0 - m0n);
        const float c1 = ex2(m1 - m1n);
        l0 *= c0; l1 *= c1;
        m0 = m0n; m1 = m1n;
#pragma unroll
        for (int nt = 0; nt < 8; nt++) {
            accv[nt][0] *= c0; accv[nt][1] *= c0;
            accv[nt][2] *= c1; accv[nt][3] *= c1;
        }

        uint32_t aPh[4][4], aPl[4][4];
        const int kbase = kt * 64 + colq;
#pragma unroll
        for (int nt = 0; nt < 8; nt++) {
            const int kc = kbase + nt * 8;
            const float2 g0 = *(const float2*)(gmRow0 + kc);
            const float2 g1 = *(const float2*)(gmRow1 + kc);
            const float p00 = ex2(s[nt][0] - m0);
            const float p01 = ex2(s[nt][1] - m0);
            const float p10 = ex2(s[nt][2] - m1);
            const float p11 = ex2(s[nt][3] - m1);
            l0 += (g0.x >= 0.0f ? p00 : 0.0f) + (g0.y >= 0.0f ? p01 : 0.0f);
            l1 += (g1.x >= 0.0f ? p10 : 0.0f) + (g1.y >= 0.0f ? p11 : 0.0f);
            const float w00 = p00 * fmaxf(g0.x, 0.0f);
            const float w01 = p01 * fmaxf(g0.y, 0.0f);
            const float w10 = p10 * fmaxf(g1.x, 0.0f);
            const float w11 = p11 * fmaxf(g1.y, 0.0f);
            const int ks = nt >> 1, half = (nt & 1) * 2;
            split2(w00, w01, aPh[ks][half + 0], aPl[ks][half + 0]);
            split2(w10, w11, aPh[ks][half + 1], aPl[ks][half + 1]);
        }

        // ---- acc += P V (bf16x3, V via ldmatrix.trans) ----
#pragma unroll
        for (int ks = 0; ks < 4; ks++) {
#pragma unroll
            for (int ng = 0; ng < 4; ng++) {
                const int row = ks * 16 + ((lg & 1) ? 8 : 0) + l8;
                const int col = ng * 16 + ((lg >> 1) ? 8 : 0);
                const uint32_t d = swz((uint32_t)row * 128 + col * 2);
                uint32_t vh4[4], vl4[4];
                ldm_x4_t(vh4, stg + 16384 + d);
                ldm_x4_t(vl4, stg + 24576 + d);
                uint32_t bh0[2] = {vh4[0], vh4[1]}, bh1[2] = {vh4[2], vh4[3]};
                uint32_t bl0[2] = {vl4[0], vl4[1]}, bl1[2] = {vl4[2], vl4[3]};
                mma_bf16(accv[ng * 2],     aPh[ks], bh0);
                mma_bf16(accv[ng * 2],     aPh[ks], bl0);
                mma_bf16(accv[ng * 2],     aPl[ks], bh0);
                mma_bf16(accv[ng * 2 + 1], aPh[ks], bh1);
                mma_bf16(accv[ng * 2 + 1], aPh[ks], bl1);
                mma_bf16(accv[ng * 2 + 1], aPl[ks], bh1);
            }
        }

        // ---- pipeline advance ----
        __syncthreads();
        if (kt + 2 < SEQ / 64) load_stage(kt + 2, st);
        asm volatile("cp.async.commit_group;" ::: "memory");
        if (kt + 1 < SEQ / 64) {
            asm volatile("cp.async.wait_group 1;" ::: "memory");
            __syncthreads();
        }
    }

    // ---- epilogue ----
    l0 += __shfl_xor_sync(0xffffffffu, l0, 1);
    l0 += __shfl_xor_sync(0xffffffffu, l0, 2);
    l1 += __shfl_xor_sync(0xffffffffu, l1, 1);
    l1 += __shfl_xor_sync(0xffffffffu, l1, 2);
    const float inv0 = 1.0f / l0, inv1 = 1.0f / l1;

    const size_t tok0 = (size_t)b * SEQ + qrow0;
    __nv_bfloat16* ch0 = g_ch + tok0 * DMODEL + h * DHEAD + colq;
    __nv_bfloat16* cl0 = g_cl + tok0 * DMODEL + h * DHEAD + colq;
#pragma unroll
    for (int nt = 0; nt < 8; nt++) {
        uint32_t hi, lo;
        split2(accv[nt][0] * inv0, accv[nt][1] * inv0, hi, lo);
        *(uint32_t*)(ch0 + nt * 8) = hi;
        *(uint32_t*)(cl0 + nt * 8) = lo;
        split2(accv[nt][2] * inv1, accv[nt][3] * inv1, hi, lo);
        *(uint32_t*)(ch0 + 8 * DMODEL + nt * 8) = hi;
        *(uint32_t*)(cl0 + 8 * DMODEL + nt * 8) = lo;
    }
}

// ---------------------------------------------------------------------------
extern "C" void kernel_launch(void* const* d_in, const int* in_sizes, int n_in,
                              void* d_out, int out_size)
{
    (void)in_sizes; (void)n_in; (void)out_size;
    const float* query = (const float*)d_in[0];
    const float* key_  = (const float*)d_in[1];
    const float* value = (const float*)d_in[2];
    const int*   mask  = (const int*)  d_in[3];
    const float* group = (const float*)d_in[4];
    const float* Wq = (const float*)d_in[5];
    const float* bq = (const float*)d_in[6];
    const float* Wk = (const float*)d_in[7];
    const float* bk = (const float*)d_in[8];
    const float* Wv = (const float*)d_in[9];
    const float* bv = (const float*)d_in[10];
    const float* Wo = (const float*)d_in[11];
    const float* bo = (const float*)d_in[12];
    float* out = (float*)d_out;

    __nv_bfloat16 *qh, *ql, *kh, *kl, *vh, *vl, *ch, *cl;
    __nv_bfloat16 *wqh, *wql, *wkh, *wkl, *wvh, *wvl, *woh, *wol;
    __nv_bfloat16 *oqh, *oql, *okh, *okl, *ovh, *ovl;
    float* gmp;
    cudaGetSymbolAddress((void**)&qh, g_qh);   cudaGetSymbolAddress((void**)&ql, g_ql);
    cudaGetSymbolAddress((void**)&kh, g_kh);   cudaGetSymbolAddress((void**)&kl, g_kl);
    cudaGetSymbolAddress((void**)&vh, g_vh);   cudaGetSymbolAddress((void**)&vl, g_vl);
    cudaGetSymbolAddress((void**)&ch, g_ch);   cudaGetSymbolAddress((void**)&cl, g_cl);
    cudaGetSymbolAddress((void**)&wqh, g_wqh); cudaGetSymbolAddress((void**)&wql, g_wql);
    cudaGetSymbolAddress((void**)&wkh, g_wkh); cudaGetSymbolAddress((void**)&wkl, g_wkl);
    cudaGetSymbolAddress((void**)&wvh, g_wvh); cudaGetSymbolAddress((void**)&wvl, g_wvl);
    cudaGetSymbolAddress((void**)&woh, g_woh); cudaGetSymbolAddress((void**)&wol, g_wol);
    cudaGetSymbolAddress((void**)&oqh, g_oqh); cudaGetSymbolAddress((void**)&oql, g_oql);
    cudaGetSymbolAddress((void**)&okh, g_okh); cudaGetSymbolAddress((void**)&okl, g_okl);
    cudaGetSymbolAddress((void**)&ovh, g_ovh); cudaGetSymbolAddress((void**)&ovl, g_ovl);
    cudaGetSymbolAddress((void**)&gmp, g_gm);

    cudaFuncSetAttribute(gemm_kernel, cudaFuncAttributeMaxDynamicSharedMemorySize,
                         GEMM_SMEM);
    cudaFuncSetAttribute(attn_kernel, cudaFuncAttributeMaxDynamicSharedMemorySize,
                         ATT_SMEM);

    const int actBlocks = NTOK / 2;
    const int wBlocks   = DMODEL / 2;

    cvt_kernel<<<actBlocks, 256>>>(query, qh, ql, NTOK);
    cvt_kernel<<<actBlocks, 256>>>(key_,  kh, kl, NTOK);
    cvt_kernel<<<actBlocks, 256>>>(value, vh, vl, NTOK);
    cvt_kernel<<<wBlocks, 256>>>(Wq, wqh, wql, DMODEL);
    cvt_kernel<<<wBlocks, 256>>>(Wk, wkh, wkl, DMODEL);
    cvt_kernel<<<wBlocks, 256>>>(Wv, wvh, wvl, DMODEL);
    cvt_kernel<<<wBlocks, 256>>>(Wo, woh, wol, DMODEL);
    prep_gm_kernel<<<BATCH * SEQ * SEQ / 4 / 256, 256>>>(mask, group, gmp);

    const float QSCALE = 0.125f * 1.44269504088896f;  // 1/sqrt(DK) * log2(e)
    const dim3 gg(DMODEL / BN, NTOK / BM);
    gemm_kernel<<<gg, 256, GEMM_SMEM>>>(qh, ql, wqh, wql, bq, nullptr, oqh, oql, 1, QSCALE);
    gemm_kernel<<<gg, 256, GEMM_SMEM>>>(kh, kl, wkh, wkl, bk, nullptr, okh, okl, 1, 1.0f);
    gemm_kernel<<<gg, 256, GEMM_SMEM>>>(vh, vl, wvh, wvl, bv, nullptr, ovh, ovl, 1, 1.0f);

    attn_kernel<<<dim3(NHEAD, SEQ / 128, BATCH), 256, ATT_SMEM>>>(gmp);

    gemm_kernel<<<gg, 256, GEMM_SMEM>>>(ch, cl, woh, wol, bo, out, nullptr, nullptr, 0, 1.0f);
}

// round 6
// speedup vs baseline: 2.9575x; 1.1208x over previous
#include <cuda_runtime.h>
#include <cuda_bf16.h>
#include <math.h>
#include <stdint.h>

#define BATCH  4
#define SEQ    1024
#define DMODEL 1024
#define NHEAD  16
#define DHEAD  64
#define NTOK   (BATCH * SEQ)

// ---------------- scratch (device globals; no runtime alloc) ----------------
__device__ __nv_bfloat16 g_qh[NTOK * DMODEL], g_ql[NTOK * DMODEL];
__device__ __nv_bfloat16 g_kh[NTOK * DMODEL], g_kl[NTOK * DMODEL];
__device__ __nv_bfloat16 g_vh[NTOK * DMODEL], g_vl[NTOK * DMODEL];
__device__ __nv_bfloat16 g_wqh[DMODEL * DMODEL], g_wql[DMODEL * DMODEL];
__device__ __nv_bfloat16 g_wkh[DMODEL * DMODEL], g_wkl[DMODEL * DMODEL];
__device__ __nv_bfloat16 g_wvh[DMODEL * DMODEL], g_wvl[DMODEL * DMODEL];
__device__ __nv_bfloat16 g_woh[DMODEL * DMODEL], g_wol[DMODEL * DMODEL];
// projected Q/K/V hi/lo in [b,h,s,64] layout  (Q pre-scaled by 0.125*log2e)
__device__ __nv_bfloat16 g_oqh[NTOK * DMODEL], g_oql[NTOK * DMODEL];
__device__ __nv_bfloat16 g_okh[NTOK * DMODEL], g_okl[NTOK * DMODEL];
__device__ __nv_bfloat16 g_ovh[NTOK * DMODEL], g_ovl[NTOK * DMODEL];
// attention context hi/lo, row-major [tok][1024]
__device__ __nv_bfloat16 g_ch[NTOK * DMODEL], g_cl[NTOK * DMODEL];
// fused mask*group: allowed ? group : -1
__device__ float g_gm[BATCH * SEQ * SEQ];

// ---------------------------------------------------------------------------
// shared PTX helpers
// ---------------------------------------------------------------------------
__device__ __forceinline__ uint32_t s2u(const void* p) {
    uint32_t a;
    asm("{ .reg .u64 t; cvta.to.shared.u64 t, %1; cvt.u32.u64 %0, t; }"
        : "=r"(a) : "l"(p));
    return a;
}
__device__ __forceinline__ void cp16(uint32_t dst, const void* src) {
    asm volatile("cp.async.cg.shared.global [%0], [%1], 16;" :: "r"(dst), "l"(src));
}
__device__ __forceinline__ void ldm_x4(uint32_t* r, uint32_t addr) {
    asm volatile("ldmatrix.sync.aligned.m8n8.x4.shared.b16 {%0,%1,%2,%3}, [%4];"
                 : "=r"(r[0]), "=r"(r[1]), "=r"(r[2]), "=r"(r[3]) : "r"(addr));
}
__device__ __forceinline__ void ldm_x4_t(uint32_t* r, uint32_t addr) {
    asm volatile("ldmatrix.sync.aligned.m8n8.x4.trans.shared.b16 {%0,%1,%2,%3}, [%4];"
                 : "=r"(r[0]), "=r"(r[1]), "=r"(r[2]), "=r"(r[3]) : "r"(addr));
}
__device__ __forceinline__ void mma_bf16(float* c, const uint32_t* a,
                                         const uint32_t* b) {
    asm volatile(
        "mma.sync.aligned.m16n8k16.row.col.f32.bf16.bf16.f32 "
        "{%0,%1,%2,%3}, {%4,%5,%6,%7}, {%8,%9}, {%0,%1,%2,%3};"
        : "+f"(c[0]), "+f"(c[1]), "+f"(c[2]), "+f"(c[3])
        : "r"(a[0]), "r"(a[1]), "r"(a[2]), "r"(a[3]), "r"(b[0]), "r"(b[1]));
}
__device__ __forceinline__ uint32_t swz(uint32_t byte) {
    return byte ^ ((byte >> 3) & 0x70);
}
__device__ __forceinline__ void split2(float x, float y, uint32_t& hi, uint32_t& lo) {
    asm("cvt.rn.bf16x2.f32 %0, %1, %2;" : "=r"(hi) : "f"(y), "f"(x));
    const float xr = x - __uint_as_float(hi << 16);
    const float yr = y - __uint_as_float(hi & 0xffff0000u);
    asm("cvt.rn.bf16x2.f32 %0, %1, %2;" : "=r"(lo) : "f"(yr), "f"(xr));
}
__device__ __forceinline__ float ex2(float x) {
    float r;
    asm("ex2.approx.f32 %0, %1;" : "=f"(r) : "f"(x));
    return r;
}

// ---------------------------------------------------------------------------
// conversions (merged launches)
// ---------------------------------------------------------------------------
__device__ __forceinline__ void cvt_body(const float* __restrict__ src,
                                         __nv_bfloat16* __restrict__ hi,
                                         __nv_bfloat16* __restrict__ lo, int t)
{
    const int idx = t * 8;
    const float4 a = *(const float4*)(src + idx);
    const float4 b = *(const float4*)(src + idx + 4);
    const float f[8] = {a.x, a.y, a.z, a.w, b.x, b.y, b.z, b.w};
    union { __nv_bfloat16 h[8]; uint4 u; } ph, pl;
#pragma unroll
    for (int i = 0; i < 8; i++) {
        const __nv_bfloat16 hh = __float2bfloat16(f[i]);
        ph.h[i] = hh;
        pl.h[i] = __float2bfloat16(f[i] - __bfloat162float(hh));
    }
    *(uint4*)(hi + idx) = ph.u;
    *(uint4*)(lo + idx) = pl.u;
}

// activations: z=0 query, 1 key, 2 value
__global__ __launch_bounds__(256) void cvt_act_kernel(
    const float* __restrict__ s0, const float* __restrict__ s1,
    const float* __restrict__ s2)
{
    const int t = blockIdx.x * 256 + threadIdx.x;
    if (t >= NTOK * (DMODEL / 8)) return;
    const int z = blockIdx.y;
    const float* src = (z == 0) ? s0 : (z == 1) ? s1 : s2;
    __nv_bfloat16* hi = (z == 0) ? g_qh : (z == 1) ? g_kh : g_vh;
    __nv_bfloat16* lo = (z == 0) ? g_ql : (z == 1) ? g_kl : g_vl;
    cvt_body(src, hi, lo, t);
}

// weights: z=0 Wq, 1 Wk, 2 Wv, 3 Wo
__global__ __launch_bounds__(256) void cvt_w_kernel(
    const float* __restrict__ s0, const float* __restrict__ s1,
    const float* __restrict__ s2, const float* __restrict__ s3)
{
    const int t = blockIdx.x * 256 + threadIdx.x;
    if (t >= DMODEL * (DMODEL / 8)) return;
    const int z = blockIdx.y;
    const float* src = (z == 0) ? s0 : (z == 1) ? s1 : (z == 2) ? s2 : s3;
    __nv_bfloat16* hi = (z == 0) ? g_wqh : (z == 1) ? g_wkh : (z == 2) ? g_wvh : g_woh;
    __nv_bfloat16* lo = (z == 0) ? g_wql : (z == 1) ? g_wkl : (z == 2) ? g_wvl : g_wol;
    cvt_body(src, hi, lo, t);
}

// gm = (mask || q==k) ? group : -1
__global__ __launch_bounds__(256) void prep_gm_kernel(
    const int* __restrict__ mask, const float* __restrict__ group,
    float* __restrict__ gm)
{
    const int t = blockIdx.x * 256 + threadIdx.x;
    if (t >= BATCH * SEQ * SEQ / 4) return;
    const int i = t * 4;
    const int q = (i >> 10) & 1023;
    const int k = i & 1023;
    const int4   mk = *(const int4*)(mask + i);
    const float4 gr = *(const float4*)(group + i);
    float4 o;
    o.x = (mk.x || q == k + 0) ? gr.x : -1.0f;
    o.y = (mk.y || q == k + 1) ? gr.y : -1.0f;
    o.z = (mk.z || q == k + 2) ? gr.z : -1.0f;
    o.w = (mk.w || q == k + 3) ? gr.w : -1.0f;
    *(float4*)(gm + i) = o;
}

// ---------------------------------------------------------------------------
// bf16x3 GEMM body. BK=64, 3 stages (216KB smem), 256 threads, 8 warps 2x4.
// out[r, c] = sum_k A[r,k] * W[c,k] + bias[c]
// ---------------------------------------------------------------------------
#define BM 128
#define BN 128
#define BK 64
#define STAGES 3
#define KTILES (DMODEL / BK)          // 16
#define PAD_B 144                     // bytes per smem row (128 data + 16 pad)
#define TILE_B (128 * PAD_B)          // 18432
#define STAGE_B (4 * TILE_B)          // 73728
#define GEMM_SMEM (STAGES * STAGE_B)  // 221184

__device__ __forceinline__ void gemm_body(
    const __nv_bfloat16* __restrict__ aH, const __nv_bfloat16* __restrict__ aL,
    const __nv_bfloat16* __restrict__ bH, const __nv_bfloat16* __restrict__ bL,
    const float* __restrict__ bias, float* __restrict__ outF,
    __nv_bfloat16* __restrict__ outH, __nv_bfloat16* __restrict__ outL,
    int mode, float oscale, int brow, int bcol, char* smem)
{
    const uint32_t sb = s2u(smem);
    const int tid  = threadIdx.x;
    const int lane = tid & 31;
    const int wid  = tid >> 5;
    const int warpM = wid >> 2;
    const int warpN = wid & 3;

    float acc[4][4][4];
#pragma unroll
    for (int i = 0; i < 4; i++)
#pragma unroll
        for (int j = 0; j < 4; j++)
#pragma unroll
            for (int k = 0; k < 4; k++) acc[i][j][k] = 0.0f;

    auto load_stage = [&](int kb, int s) {
        const int k0 = kb * BK;
        const uint32_t base = sb + (uint32_t)s * STAGE_B;
#pragma unroll
        for (int i = 0; i < 4; i++) {
            const int c = tid + i * 256;       // 0..1023
            const int r = c >> 3;              // row 0..127
            const int q = c & 7;               // 16B chunk in 128B row
            const uint32_t dst = base + (uint32_t)r * PAD_B + q * 16;
            const size_t aoff = (size_t)(brow + r) * DMODEL + k0 + q * 8;
            const size_t boff = (size_t)(bcol + r) * DMODEL + k0 + q * 8;
            cp16(dst,              aH + aoff);
            cp16(dst + TILE_B,     aL + aoff);
            cp16(dst + 2 * TILE_B, bH + boff);
            cp16(dst + 3 * TILE_B, bL + boff);
        }
        asm volatile("cp.async.commit_group;" ::: "memory");
    };

    const int l8 = lane & 7, lg = lane >> 3;
    const int a_row_off = ((lg & 1) ? 8 : 0) + l8;
    const int a_col_off = (lg & 2) ? 8 : 0;
    const int b_row_off = ((lg >> 1) ? 8 : 0) + l8;
    const int b_col_off = (lg & 1) ? 8 : 0;

    for (int s = 0; s < STAGES - 1; s++) load_stage(s, s);

    for (int kb = 0; kb < KTILES; kb++) {
        asm volatile("cp.async.wait_group %0;" :: "n"(STAGES - 2));
        __syncthreads();
        if (kb + STAGES - 1 < KTILES)
            load_stage(kb + STAGES - 1, (kb + STAGES - 1) % STAGES);
        else
            asm volatile("cp.async.commit_group;" ::: "memory");

        const uint32_t stg = sb + (uint32_t)(kb % STAGES) * STAGE_B;
#pragma unroll
        for (int ks = 0; ks < 4; ks++) {
            uint32_t ah[4][4], al[4][4], bh[4][2], bl[4][2];
#pragma unroll
            for (int mt = 0; mt < 4; mt++) {
                const int row = warpM * 64 + mt * 16 + a_row_off;
                const int col = ks * 16 + a_col_off;
                const uint32_t ad = stg + (uint32_t)row * PAD_B + col * 2;
                ldm_x4(ah[mt], ad);
                ldm_x4(al[mt], ad + TILE_B);
            }
#pragma unroll
            for (int pt = 0; pt < 2; pt++) {
                const int n   = warpN * 32 + pt * 16 + b_row_off;
                const int col = ks * 16 + b_col_off;
                const uint32_t bd = stg + 2 * TILE_B + (uint32_t)n * PAD_B + col * 2;
                uint32_t t[4];
                ldm_x4(t, bd);
                bh[pt * 2][0] = t[0]; bh[pt * 2][1] = t[1];
                bh[pt * 2 + 1][0] = t[2]; bh[pt * 2 + 1][1] = t[3];
                ldm_x4(t, bd + TILE_B);
                bl[pt * 2][0] = t[0]; bl[pt * 2][1] = t[1];
                bl[pt * 2 + 1][0] = t[2]; bl[pt * 2 + 1][1] = t[3];
            }
#pragma unroll
            for (int mt = 0; mt < 4; mt++)
#pragma unroll
                for (int nt = 0; nt < 4; nt++) {
                    mma_bf16(acc[mt][nt], ah[mt], bh[nt]);
                    mma_bf16(acc[mt][nt], ah[mt], bl[nt]);
                    mma_bf16(acc[mt][nt], al[mt], bh[nt]);
                }
        }
    }

#pragma unroll
    for (int mt = 0; mt < 4; mt++) {
        const int row = brow + warpM * 64 + mt * 16 + (lane >> 2);
#pragma unroll
        for (int nt = 0; nt < 4; nt++) {
            const int col = bcol + warpN * 32 + nt * 8 + (lane & 3) * 2;
            const float b0 = bias[col], b1 = bias[col + 1];
            const float v00 = acc[mt][nt][0] + b0, v01 = acc[mt][nt][1] + b1;
            const float v10 = acc[mt][nt][2] + b0, v11 = acc[mt][nt][3] + b1;
            if (mode == 0) {
                *(float2*)(outF + (size_t)row * DMODEL + col) = make_float2(v00, v01);
                *(float2*)(outF + (size_t)(row + 8) * DMODEL + col) = make_float2(v10, v11);
            } else {
                const int h = col >> 6, dk = col & 63;
                const int bi = row >> 10, s = row & 1023;
                const size_t d0 = (((size_t)(bi * NHEAD + h)) * SEQ + s) * DHEAD + dk;
                uint32_t hi, lo;
                split2(v00 * oscale, v01 * oscale, hi, lo);
                *(uint32_t*)(outH + d0) = hi;
                *(uint32_t*)(outL + d0) = lo;
                split2(v10 * oscale, v11 * oscale, hi, lo);
                *(uint32_t*)(outH + d0 + 8 * DHEAD) = hi;
                *(uint32_t*)(outL + d0 + 8 * DHEAD) = lo;
            }
        }
    }
}

// Q/K/V projections in one launch; z selects operand set.
__global__ __launch_bounds__(256, 1) void gemm_qkv_kernel(
    const float* __restrict__ bq, const float* __restrict__ bk,
    const float* __restrict__ bv, float qscale)
{
    extern __shared__ __align__(16) char smem[];
    const int z = blockIdx.z;
    const __nv_bfloat16 *aH, *aL, *bH, *bL;
    __nv_bfloat16 *oH, *oL;
    const float* bias;
    float sc;
    if (z == 0)      { aH = g_qh; aL = g_ql; bH = g_wqh; bL = g_wql;
                       oH = g_oqh; oL = g_oql; bias = bq; sc = qscale; }
    else if (z == 1) { aH = g_kh; aL = g_kl; bH = g_wkh; bL = g_wkl;
                       oH = g_okh; oL = g_okl; bias = bk; sc = 1.0f; }
    else             { aH = g_vh; aL = g_vl; bH = g_wvh; bL = g_wvl;
                       oH = g_ovh; oL = g_ovl; bias = bv; sc = 1.0f; }
    gemm_body(aH, aL, bH, bL, bias, nullptr, oH, oL, 1, sc,
              blockIdx.y * BM, blockIdx.x * BN, smem);
}

// final output projection
__global__ __launch_bounds__(256, 1) void gemm_out_kernel(
    const float* __restrict__ bo, float* __restrict__ out)
{
    extern __shared__ __align__(16) char smem[];
    gemm_body(g_ch, g_cl, g_woh, g_wol, bo, out, nullptr, nullptr, 0, 1.0f,
              blockIdx.y * BM, blockIdx.x * BN, smem);
}

// ---------------------------------------------------------------------------
// Tensor-core flash attention (log2-domain softmax; Q pre-scaled by .125*log2e)
// CTA = 128 q-rows x one (b,h); 8 warps x 16 rows; 64-key double-buffered tiles.
// ---------------------------------------------------------------------------
#define ATT_QH 0
#define ATT_QL 16384
#define ATT_STG0 32768
#define ATT_STG_B 32768
#define ATT_SMEM (32768 + 2 * ATT_STG_B)   // 98304

__global__ __launch_bounds__(256, 2) void attn_kernel(const float* __restrict__ gm)
{
    extern __shared__ __align__(16) char smem[];
    const uint32_t sb = s2u(smem);
    const int tid  = threadIdx.x;
    const int lane = tid & 31;
    const int w    = tid >> 5;
    const int h    = blockIdx.x;
    const int q0   = blockIdx.y * 128;
    const int b    = blockIdx.z;
    const int bh   = b * NHEAD + h;

    const __nv_bfloat16* Qh = g_oqh + ((size_t)bh * SEQ + q0) * DHEAD;
    const __nv_bfloat16* Ql = g_oql + ((size_t)bh * SEQ + q0) * DHEAD;
    const __nv_bfloat16* Kh = g_okh + (size_t)bh * SEQ * DHEAD;
    const __nv_bfloat16* Kl = g_okl + (size_t)bh * SEQ * DHEAD;
    const __nv_bfloat16* Vh = g_ovh + (size_t)bh * SEQ * DHEAD;
    const __nv_bfloat16* Vl = g_ovl + (size_t)bh * SEQ * DHEAD;

#pragma unroll
    for (int i = 0; i < 4; i++) {
        const int c = tid + i * 256;
        const int r = c >> 3, off = c & 7;
        const uint32_t d = swz((uint32_t)r * 128 + off * 16);
        cp16(sb + ATT_QH + d, Qh + (size_t)r * DHEAD + off * 8);
        cp16(sb + ATT_QL + d, Ql + (size_t)r * DHEAD + off * 8);
    }
    auto load_stage = [&](int kt, int s) {
        const int k0 = kt * 64;
        const uint32_t base = sb + ATT_STG0 + (uint32_t)s * ATT_STG_B;
#pragma unroll
        for (int i = 0; i < 2; i++) {
            const int c = tid + i * 256;
            const int r = c >> 3, off = c & 7;
            const uint32_t d = swz((uint32_t)r * 128 + off * 16);
            const size_t g = (size_t)(k0 + r) * DHEAD + off * 8;
            cp16(base + d,         Kh + g);
            cp16(base + 8192 + d,  Kl + g);
            cp16(base + 16384 + d, Vh + g);
            cp16(base + 24576 + d, Vl + g);
        }
    };
    load_stage(0, 0);
    asm volatile("cp.async.commit_group;" ::: "memory");
    load_stage(1, 1);
    asm volatile("cp.async.commit_group;" ::: "memory");
    asm volatile("cp.async.wait_group 1;" ::: "memory");
    __syncthreads();

    const int l8 = lane & 7, lg = lane >> 3;
    const int a_row_off = ((lg & 1) ? 8 : 0) + l8;
    const int a_col_off = (lg & 2) ? 8 : 0;
    const int b_row_off = ((lg >> 1) ? 8 : 0) + l8;
    const int b_col_off = (lg & 1) ? 8 : 0;

    uint32_t qfh[4][4];
    const uint32_t qrowbyte = (uint32_t)(w * 16 + a_row_off) * 128;
#pragma unroll
    for (int ks = 0; ks < 4; ks++) {
        const uint32_t d = swz(qrowbyte + (ks * 16 + a_col_off) * 2);
        ldm_x4(qfh[ks], sb + ATT_QH + d);
    }

    float accv[8][4];
#pragma unroll
    for (int i = 0; i < 8; i++)
#pragma unroll
        for (int j = 0; j < 4; j++) accv[i][j] = 0.0f;
    float m0 = -INFINITY, m1 = -INFINITY, l0 = 0.0f, l1 = 0.0f;

    const int r0 = lane >> 2;
    const int qrow0 = q0 + w * 16 + r0;
    const float* gmRow0 = gm + ((size_t)b * SEQ + qrow0) * SEQ;
    const float* gmRow1 = gmRow0 + 8 * SEQ;
    const int colq = (lane & 3) * 2;

    for (int kt = 0; kt < SEQ / 64; kt++) {
        const int st = kt & 1;
        const uint32_t stg = sb + ATT_STG0 + (uint32_t)st * ATT_STG_B;

        float s[8][4];
#pragma unroll
        for (int i = 0; i < 8; i++)
#pragma unroll
            for (int j = 0; j < 4; j++) s[i][j] = 0.0f;
#pragma unroll
        for (int ks = 0; ks < 4; ks++) {
            uint32_t qfl[4];
            ldm_x4(qfl, sb + ATT_QL + swz(qrowbyte + (ks * 16 + a_col_off) * 2));
#pragma unroll
            for (int g16 = 0; g16 < 4; g16++) {
                const int row = g16 * 16 + b_row_off;
                const int col = ks * 16 + b_col_off;
                const uint32_t d = swz((uint32_t)row * 128 + col * 2);
                uint32_t kh4[4], kl4[4];
                ldm_x4(kh4, stg + d);
                ldm_x4(kl4, stg + 8192 + d);
                uint32_t bh0[2] = {kh4[0], kh4[1]}, bh1[2] = {kh4[2], kh4[3]};
                uint32_t bl0[2] = {kl4[0], kl4[1]}, bl1[2] = {kl4[2], kl4[3]};
                mma_bf16(s[g16 * 2],     qfh[ks], bh0);
                mma_bf16(s[g16 * 2],     qfh[ks], bl0);
                mma_bf16(s[g16 * 2],     qfl,     bh0);
                mma_bf16(s[g16 * 2 + 1], qfh[ks], bh1);
                mma_bf16(s[g16 * 2 + 1], qfh[ks], bl1);
                mma_bf16(s[g16 * 2 + 1], qfl,     bh1);
            }
        }

        float rm0 = -INFINITY, rm1 = -INFINITY;
#pragma unroll
        for (int nt = 0; nt < 8; nt++) {
            rm0 = fmaxf(rm0, fmaxf(s[nt][0], s[nt][1]));
            rm1 = fmaxf(rm1, fmaxf(s[nt][2], s[nt][3]));
        }
        rm0 = fmaxf(rm0, __shfl_xor_sync(0xffffffffu, rm0, 1));
        rm0 = fmaxf(rm0, __shfl_xor_sync(0xffffffffu, rm0, 2));
        rm1 = fmaxf(rm1, __shfl_xor_sync(0xffffffffu, rm1, 1));
        rm1 = fmaxf(rm1, __shfl_xor_sync(0xffffffffu, rm1, 2));
        const float m0n = fmaxf(m0, rm0);
        const float m1n = fmaxf(m1, rm1);
        const float c0 = ex2(m0 - m0n);
        const float c1 = ex2(m1 - m1n);
        l0 *= c0; l1 *= c1;
        m0 = m0n; m1 = m1n;
#pragma unroll
        for (int nt = 0; nt < 8; nt++) {
            accv[nt][0] *= c0; accv[nt][1] *= c0;
            accv[nt][2] *= c1; accv[nt][3] *= c1;
        }

        uint32_t aPh[4][4], aPl[4][4];
        const int kbase = kt * 64 + colq;
#pragma unroll
        for (int nt = 0; nt < 8; nt++) {
            const int kc = kbase + nt * 8;
            const float2 g0 = *(const float2*)(gmRow0 + kc);
            const float2 g1 = *(const float2*)(gmRow1 + kc);
            const float p00 = ex2(s[nt][0] - m0);
            const float p01 = ex2(s[nt][1] - m0);
            const float p10 = ex2(s[nt][2] - m1);
            const float p11 = ex2(s[nt][3] - m1);
            l0 += (g0.x >= 0.0f ? p00 : 0.0f) + (g0.y >= 0.0f ? p01 : 0.0f);
            l1 += (g1.x >= 0.0f ? p10 : 0.0f) + (g1.y >= 0.0f ? p11 : 0.0f);
            const float w00 = p00 * fmaxf(g0.x, 0.0f);
            const float w01 = p01 * fmaxf(g0.y, 0.0f);
            const float w10 = p10 * fmaxf(g1.x, 0.0f);
            const float w11 = p11 * fmaxf(g1.y, 0.0f);
            const int ks = nt >> 1, half = (nt & 1) * 2;
            split2(w00, w01, aPh[ks][half + 0], aPl[ks][half + 0]);
            split2(w10, w11, aPh[ks][half + 1], aPl[ks][half + 1]);
        }

#pragma unroll
        for (int ks = 0; ks < 4; ks++) {
#pragma unroll
            for (int ng = 0; ng < 4; ng++) {
                const int row = ks * 16 + ((lg & 1) ? 8 : 0) + l8;
                const int col = ng * 16 + ((lg >> 1) ? 8 : 0);
                const uint32_t d = swz((uint32_t)row * 128 + col * 2);
                uint32_t vh4[4], vl4[4];
                ldm_x4_t(vh4, stg + 16384 + d);
                ldm_x4_t(vl4, stg + 24576 + d);
                uint32_t bh0[2] = {vh4[0], vh4[1]}, bh1[2] = {vh4[2], vh4[3]};
                uint32_t bl0[2] = {vl4[0], vl4[1]}, bl1[2] = {vl4[2], vl4[3]};
                mma_bf16(accv[ng * 2],     aPh[ks], bh0);
                mma_bf16(accv[ng * 2],     aPh[ks], bl0);
                mma_bf16(accv[ng * 2],     aPl[ks], bh0);
                mma_bf16(accv[ng * 2 + 1], aPh[ks], bh1);
                mma_bf16(accv[ng * 2 + 1], aPh[ks], bl1);
                mma_bf16(accv[ng * 2 + 1], aPl[ks], bh1);
            }
        }

        __syncthreads();
        if (kt + 2 < SEQ / 64) load_stage(kt + 2, st);
        asm volatile("cp.async.commit_group;" ::: "memory");
        if (kt + 1 < SEQ / 64) {
            asm volatile("cp.async.wait_group 1;" ::: "memory");
            __syncthreads();
        }
    }

    l0 += __shfl_xor_sync(0xffffffffu, l0, 1);
    l0 += __shfl_xor_sync(0xffffffffu, l0, 2);
    l1 += __shfl_xor_sync(0xffffffffu, l1, 1);
    l1 += __shfl_xor_sync(0xffffffffu, l1, 2);
    const float inv0 = 1.0f / l0, inv1 = 1.0f / l1;

    const size_t tok0 = (size_t)b * SEQ + qrow0;
    __nv_bfloat16* ch0 = g_ch + tok0 * DMODEL + h * DHEAD + colq;
    __nv_bfloat16* cl0 = g_cl + tok0 * DMODEL + h * DHEAD + colq;
#pragma unroll
    for (int nt = 0; nt < 8; nt++) {
        uint32_t hi, lo;
        split2(accv[nt][0] * inv0, accv[nt][1] * inv0, hi, lo);
        *(uint32_t*)(ch0 + nt * 8) = hi;
        *(uint32_t*)(cl0 + nt * 8) = lo;
        split2(accv[nt][2] * inv1, accv[nt][3] * inv1, hi, lo);
        *(uint32_t*)(ch0 + 8 * DMODEL + nt * 8) = hi;
        *(uint32_t*)(cl0 + 8 * DMODEL + nt * 8) = lo;
    }
}

// ---------------------------------------------------------------------------
extern "C" void kernel_launch(void* const* d_in, const int* in_sizes, int n_in,
                              void* d_out, int out_size)
{
    (void)in_sizes; (void)n_in; (void)out_size;
    const float* query = (const float*)d_in[0];
    const float* key_  = (const float*)d_in[1];
    const float* value = (const float*)d_in[2];
    const int*   mask  = (const int*)  d_in[3];
    const float* group = (const float*)d_in[4];
    const float* Wq = (const float*)d_in[5];
    const float* bq = (const float*)d_in[6];
    const float* Wk = (const float*)d_in[7];
    const float* bk = (const float*)d_in[8];
    const float* Wv = (const float*)d_in[9];
    const float* bv = (const float*)d_in[10];
    const float* Wo = (const float*)d_in[11];
    const float* bo = (const float*)d_in[12];
    float* out = (float*)d_out;

    float* gmp;
    cudaGetSymbolAddress((void**)&gmp, g_gm);

    cudaFuncSetAttribute(gemm_qkv_kernel, cudaFuncAttributeMaxDynamicSharedMemorySize,
                         GEMM_SMEM);
    cudaFuncSetAttribute(gemm_out_kernel, cudaFuncAttributeMaxDynamicSharedMemorySize,
                         GEMM_SMEM);
    cudaFuncSetAttribute(attn_kernel, cudaFuncAttributeMaxDynamicSharedMemorySize,
                         ATT_SMEM);

    cvt_act_kernel<<<dim3(NTOK * (DMODEL / 8) / 256, 3), 256>>>(query, key_, value);
    cvt_w_kernel<<<dim3(DMODEL * (DMODEL / 8) / 256, 4), 256>>>(Wq, Wk, Wv, Wo);
    prep_gm_kernel<<<BATCH * SEQ * SEQ / 4 / 256, 256>>>(mask, group, gmp);

    const float QSCALE = 0.125f * 1.44269504088896f;  // 1/sqrt(DK) * log2(e)
    gemm_qkv_kernel<<<dim3(DMODEL / BN, NTOK / BM, 3), 256, GEMM_SMEM>>>(
        bq, bk, bv, QSCALE);

    attn_kernel<<<dim3(NHEAD, SEQ / 128, BATCH), 256, ATT_SMEM>>>(gmp);

    gemm_out_kernel<<<dim3(DMODEL / BN, NTOK / BM), 256, GEMM_SMEM>>>(bo, out);
}

// round 7
// speedup vs baseline: 3.0476x; 1.0305x over previous
#include <cuda_runtime.h>
#include <cuda_bf16.h>
#include <math.h>
#include <stdint.h>

#define BATCH  4
#define SEQ    1024
#define DMODEL 1024
#define NHEAD  16
#define DHEAD  64
#define NTOK   (BATCH * SEQ)

// ---------------- scratch (device globals; no runtime alloc) ----------------
__device__ __nv_bfloat16 g_qh[NTOK * DMODEL], g_ql[NTOK * DMODEL];
__device__ __nv_bfloat16 g_kh[NTOK * DMODEL], g_kl[NTOK * DMODEL];
__device__ __nv_bfloat16 g_vh[NTOK * DMODEL], g_vl[NTOK * DMODEL];
__device__ __nv_bfloat16 g_wqh[DMODEL * DMODEL], g_wql[DMODEL * DMODEL];
__device__ __nv_bfloat16 g_wkh[DMODEL * DMODEL], g_wkl[DMODEL * DMODEL];
__device__ __nv_bfloat16 g_wvh[DMODEL * DMODEL], g_wvl[DMODEL * DMODEL];
__device__ __nv_bfloat16 g_woh[DMODEL * DMODEL], g_wol[DMODEL * DMODEL];
// projected Q/K/V hi/lo in [b,h,s,64] layout  (Q pre-scaled by 0.125*log2e)
__device__ __nv_bfloat16 g_oqh[NTOK * DMODEL], g_oql[NTOK * DMODEL];
__device__ __nv_bfloat16 g_okh[NTOK * DMODEL], g_okl[NTOK * DMODEL];
__device__ __nv_bfloat16 g_ovh[NTOK * DMODEL], g_ovl[NTOK * DMODEL];
// attention context hi/lo, row-major [tok][1024]
__device__ __nv_bfloat16 g_ch[NTOK * DMODEL], g_cl[NTOK * DMODEL];
// fused mask*group: allowed ? group : -1
__device__ float g_gm[BATCH * SEQ * SEQ];

// ---------------------------------------------------------------------------
// shared PTX helpers
// ---------------------------------------------------------------------------
__device__ __forceinline__ uint32_t s2u(const void* p) {
    uint32_t a;
    asm("{ .reg .u64 t; cvta.to.shared.u64 t, %1; cvt.u32.u64 %0, t; }"
        : "=r"(a) : "l"(p));
    return a;
}
__device__ __forceinline__ void cp16(uint32_t dst, const void* src) {
    asm volatile("cp.async.cg.shared.global [%0], [%1], 16;" :: "r"(dst), "l"(src));
}
__device__ __forceinline__ void ldm_x4(uint32_t* r, uint32_t addr) {
    asm volatile("ldmatrix.sync.aligned.m8n8.x4.shared.b16 {%0,%1,%2,%3}, [%4];"
                 : "=r"(r[0]), "=r"(r[1]), "=r"(r[2]), "=r"(r[3]) : "r"(addr));
}
__device__ __forceinline__ void ldm_x4_t(uint32_t* r, uint32_t addr) {
    asm volatile("ldmatrix.sync.aligned.m8n8.x4.trans.shared.b16 {%0,%1,%2,%3}, [%4];"
                 : "=r"(r[0]), "=r"(r[1]), "=r"(r[2]), "=r"(r[3]) : "r"(addr));
}
__device__ __forceinline__ void mma_bf16(float* c, const uint32_t* a,
                                         const uint32_t* b) {
    asm volatile(
        "mma.sync.aligned.m16n8k16.row.col.f32.bf16.bf16.f32 "
        "{%0,%1,%2,%3}, {%4,%5,%6,%7}, {%8,%9}, {%0,%1,%2,%3};"
        : "+f"(c[0]), "+f"(c[1]), "+f"(c[2]), "+f"(c[3])
        : "r"(a[0]), "r"(a[1]), "r"(a[2]), "r"(a[3]), "r"(b[0]), "r"(b[1]));
}
__device__ __forceinline__ uint32_t swz(uint32_t byte) {
    return byte ^ ((byte >> 3) & 0x70);
}
__device__ __forceinline__ void split2(float x, float y, uint32_t& hi, uint32_t& lo) {
    asm("cvt.rn.bf16x2.f32 %0, %1, %2;" : "=r"(hi) : "f"(y), "f"(x));
    const float xr = x - __uint_as_float(hi << 16);
    const float yr = y - __uint_as_float(hi & 0xffff0000u);
    asm("cvt.rn.bf16x2.f32 %0, %1, %2;" : "=r"(lo) : "f"(yr), "f"(xr));
}
__device__ __forceinline__ float ex2(float x) {
    float r;
    asm("ex2.approx.f32 %0, %1;" : "=f"(r) : "f"(x));
    return r;
}

// ---------------------------------------------------------------------------
// conversions (merged launches)
// ---------------------------------------------------------------------------
__device__ __forceinline__ void cvt_body(const float* __restrict__ src,
                                         __nv_bfloat16* __restrict__ hi,
                                         __nv_bfloat16* __restrict__ lo, int t)
{
    const int idx = t * 8;
    const float4 a = *(const float4*)(src + idx);
    const float4 b = *(const float4*)(src + idx + 4);
    const float f[8] = {a.x, a.y, a.z, a.w, b.x, b.y, b.z, b.w};
    union { __nv_bfloat16 h[8]; uint4 u; } ph, pl;
#pragma unroll
    for (int i = 0; i < 8; i++) {
        const __nv_bfloat16 hh = __float2bfloat16(f[i]);
        ph.h[i] = hh;
        pl.h[i] = __float2bfloat16(f[i] - __bfloat162float(hh));
    }
    *(uint4*)(hi + idx) = ph.u;
    *(uint4*)(lo + idx) = pl.u;
}

__global__ __launch_bounds__(256) void cvt_act_kernel(
    const float* __restrict__ s0, const float* __restrict__ s1,
    const float* __restrict__ s2)
{
    const int t = blockIdx.x * 256 + threadIdx.x;
    if (t >= NTOK * (DMODEL / 8)) return;
    const int z = blockIdx.y;
    const float* src = (z == 0) ? s0 : (z == 1) ? s1 : s2;
    __nv_bfloat16* hi = (z == 0) ? g_qh : (z == 1) ? g_kh : g_vh;
    __nv_bfloat16* lo = (z == 0) ? g_ql : (z == 1) ? g_kl : g_vl;
    cvt_body(src, hi, lo, t);
}

__global__ __launch_bounds__(256) void cvt_w_kernel(
    const float* __restrict__ s0, const float* __restrict__ s1,
    const float* __restrict__ s2, const float* __restrict__ s3)
{
    const int t = blockIdx.x * 256 + threadIdx.x;
    if (t >= DMODEL * (DMODEL / 8)) return;
    const int z = blockIdx.y;
    const float* src = (z == 0) ? s0 : (z == 1) ? s1 : (z == 2) ? s2 : s3;
    __nv_bfloat16* hi = (z == 0) ? g_wqh : (z == 1) ? g_wkh : (z == 2) ? g_wvh : g_woh;
    __nv_bfloat16* lo = (z == 0) ? g_wql : (z == 1) ? g_wkl : (z == 2) ? g_wvl : g_wol;
    cvt_body(src, hi, lo, t);
}

__global__ __launch_bounds__(256) void prep_gm_kernel(
    const int* __restrict__ mask, const float* __restrict__ group,
    float* __restrict__ gm)
{
    const int t = blockIdx.x * 256 + threadIdx.x;
    if (t >= BATCH * SEQ * SEQ / 4) return;
    const int i = t * 4;
    const int q = (i >> 10) & 1023;
    const int k = i & 1023;
    const int4   mk = *(const int4*)(mask + i);
    const float4 gr = *(const float4*)(group + i);
    float4 o;
    o.x = (mk.x || q == k + 0) ? gr.x : -1.0f;
    o.y = (mk.y || q == k + 1) ? gr.y : -1.0f;
    o.z = (mk.z || q == k + 2) ? gr.z : -1.0f;
    o.w = (mk.w || q == k + 3) ? gr.w : -1.0f;
    *(float4*)(gm + i) = o;
}

// ---------------------------------------------------------------------------
// bf16x3 GEMM. CTA tile 128x256, BK=64, 2 stages, 8 warps (2M x 4N, 64x64 warp
// tile). out[r, c] = sum_k A[r,k] * W[c,k] + bias[c]
// ---------------------------------------------------------------------------
#define BM 128
#define BN 256
#define BK 64
#define KTILES (DMODEL / BK)          // 16
#define PAD_B 144                     // bytes per smem row (128 data + 16 pad)
#define TILE_AB (128 * PAD_B)         // 18432
#define TILE_BB (256 * PAD_B)         // 36864
#define OFF_AL  TILE_AB
#define OFF_BH  (2 * TILE_AB)
#define OFF_BL  (2 * TILE_AB + TILE_BB)
#define STAGE_B (2 * TILE_AB + 2 * TILE_BB)   // 110592
#define GEMM_SMEM (2 * STAGE_B)               // 221184

__device__ __forceinline__ void gemm_body(
    const __nv_bfloat16* __restrict__ aH, const __nv_bfloat16* __restrict__ aL,
    const __nv_bfloat16* __restrict__ bH, const __nv_bfloat16* __restrict__ bL,
    const float* __restrict__ bias, float* __restrict__ outF,
    __nv_bfloat16* __restrict__ outH, __nv_bfloat16* __restrict__ outL,
    int mode, float oscale, int brow, int bcol, char* smem)
{
    const uint32_t sb = s2u(smem);
    const int tid  = threadIdx.x;
    const int lane = tid & 31;
    const int wid  = tid >> 5;
    const int warpM = wid >> 2;          // 0..1
    const int warpN = wid & 3;           // 0..3

    float acc[4][8][4];
#pragma unroll
    for (int i = 0; i < 4; i++)
#pragma unroll
        for (int j = 0; j < 8; j++)
#pragma unroll
            for (int k = 0; k < 4; k++) acc[i][j][k] = 0.0f;

    auto load_stage = [&](int kb, int s) {
        const int k0 = kb * BK;
        const uint32_t base = sb + (uint32_t)s * STAGE_B;
        // A: 128 rows x 8 chunks (hi+lo)
#pragma unroll
        for (int i = 0; i < 4; i++) {
            const int c = tid + i * 256;       // 0..1023
            const int r = c >> 3;
            const int q = c & 7;
            const uint32_t dst = base + (uint32_t)r * PAD_B + q * 16;
            const size_t aoff = (size_t)(brow + r) * DMODEL + k0 + q * 8;
            cp16(dst,          aH + aoff);
            cp16(dst + OFF_AL, aL + aoff);
        }
        // B: 256 rows x 8 chunks (hi+lo)
#pragma unroll
        for (int i = 0; i < 8; i++) {
            const int c = tid + i * 256;       // 0..2047
            const int r = c >> 3;
            const int q = c & 7;
            const uint32_t dst = base + OFF_BH + (uint32_t)r * PAD_B + q * 16;
            const size_t boff = (size_t)(bcol + r) * DMODEL + k0 + q * 8;
            cp16(dst,                     bH + boff);
            cp16(dst + (OFF_BL - OFF_BH), bL + boff);
        }
        asm volatile("cp.async.commit_group;" ::: "memory");
    };

    const int l8 = lane & 7, lg = lane >> 3;
    const int a_row_off = ((lg & 1) ? 8 : 0) + l8;
    const int a_col_off = (lg & 2) ? 8 : 0;
    const int b_row_off = ((lg >> 1) ? 8 : 0) + l8;
    const int b_col_off = (lg & 1) ? 8 : 0;

    load_stage(0, 0);
    load_stage(1, 1);
    asm volatile("cp.async.wait_group 1;" ::: "memory");
    __syncthreads();

    for (int kb = 0; kb < KTILES; kb++) {
        const uint32_t stg = sb + (uint32_t)(kb & 1) * STAGE_B;
#pragma unroll
        for (int ks = 0; ks < 4; ks++) {
            uint32_t bhf[8][2], blf[8][2];
#pragma unroll
            for (int pt = 0; pt < 4; pt++) {
                const int n   = warpN * 64 + pt * 16 + b_row_off;
                const int col = ks * 16 + b_col_off;
                const uint32_t bd = stg + OFF_BH + (uint32_t)n * PAD_B + col * 2;
                uint32_t t[4];
                ldm_x4(t, bd);
                bhf[pt * 2][0] = t[0]; bhf[pt * 2][1] = t[1];
                bhf[pt * 2 + 1][0] = t[2]; bhf[pt * 2 + 1][1] = t[3];
                ldm_x4(t, bd + (OFF_BL - OFF_BH));
                blf[pt * 2][0] = t[0]; blf[pt * 2][1] = t[1];
                blf[pt * 2 + 1][0] = t[2]; blf[pt * 2 + 1][1] = t[3];
            }
#pragma unroll
            for (int mt = 0; mt < 4; mt++) {
                const int row = warpM * 64 + mt * 16 + a_row_off;
                const int col = ks * 16 + a_col_off;
                const uint32_t ad = stg + (uint32_t)row * PAD_B + col * 2;
                uint32_t ah[4], al[4];
                ldm_x4(ah, ad);
                ldm_x4(al, ad + OFF_AL);
#pragma unroll
                for (int nt = 0; nt < 8; nt++) {
                    mma_bf16(acc[mt][nt], ah, bhf[nt]);
                    mma_bf16(acc[mt][nt], ah, blf[nt]);
                    mma_bf16(acc[mt][nt], al, bhf[nt]);
                }
            }
        }
        __syncthreads();  // all warps done reading this stage
        if (kb + 2 < KTILES) load_stage(kb + 2, kb & 1);
        else asm volatile("cp.async.commit_group;" ::: "memory");
        if (kb + 1 < KTILES) {
            asm volatile("cp.async.wait_group 1;" ::: "memory");
            __syncthreads();
        }
    }

#pragma unroll
    for (int mt = 0; mt < 4; mt++) {
        const int row = brow + warpM * 64 + mt * 16 + (lane >> 2);
#pragma unroll
        for (int nt = 0; nt < 8; nt++) {
            const int col = bcol + warpN * 64 + (nt >> 1) * 16 + (nt & 1) * 8
                          + (lane & 3) * 2;
            const float b0 = bias[col], b1 = bias[col + 1];
            const float v00 = acc[mt][nt][0] + b0, v01 = acc[mt][nt][1] + b1;
            const float v10 = acc[mt][nt][2] + b0, v11 = acc[mt][nt][3] + b1;
            if (mode == 0) {
                *(float2*)(outF + (size_t)row * DMODEL + col) = make_float2(v00, v01);
                *(float2*)(outF + (size_t)(row + 8) * DMODEL + col) = make_float2(v10, v11);
            } else {
                const int h = col >> 6, dk = col & 63;
                const int bi = row >> 10, s = row & 1023;
                const size_t d0 = (((size_t)(bi * NHEAD + h)) * SEQ + s) * DHEAD + dk;
                uint32_t hi, lo;
                split2(v00 * oscale, v01 * oscale, hi, lo);
                *(uint32_t*)(outH + d0) = hi;
                *(uint32_t*)(outL + d0) = lo;
                split2(v10 * oscale, v11 * oscale, hi, lo);
                *(uint32_t*)(outH + d0 + 8 * DHEAD) = hi;
                *(uint32_t*)(outL + d0 + 8 * DHEAD) = lo;
            }
        }
    }
}

__global__ __launch_bounds__(256, 1) void gemm_qkv_kernel(
    const float* __restrict__ bq, const float* __restrict__ bk,
    const float* __restrict__ bv, float qscale)
{
    extern __shared__ __align__(16) char smem[];
    const int z = blockIdx.z;
    const __nv_bfloat16 *aH, *aL, *bH, *bL;
    __nv_bfloat16 *oH, *oL;
    const float* bias;
    float sc;
    if (z == 0)      { aH = g_qh; aL = g_ql; bH = g_wqh; bL = g_wql;
                       oH = g_oqh; oL = g_oql; bias = bq; sc = qscale; }
    else if (z == 1) { aH = g_kh; aL = g_kl; bH = g_wkh; bL = g_wkl;
                       oH = g_okh; oL = g_okl; bias = bk; sc = 1.0f; }
    else             { aH = g_vh; aL = g_vl; bH = g_wvh; bL = g_wvl;
                       oH = g_ovh; oL = g_ovl; bias = bv; sc = 1.0f; }
    gemm_body(aH, aL, bH, bL, bias, nullptr, oH, oL, 1, sc,
              blockIdx.y * BM, blockIdx.x * BN, smem);
}

__global__ __launch_bounds__(256, 1) void gemm_out_kernel(
    const float* __restrict__ bo, float* __restrict__ out)
{
    extern __shared__ __align__(16) char smem[];
    gemm_body(g_ch, g_cl, g_woh, g_wol, bo, out, nullptr, nullptr, 0, 1.0f,
              blockIdx.y * BM, blockIdx.x * BN, smem);
}

// ---------------------------------------------------------------------------
// Tensor-core flash attention (unchanged from Round 6)
// ---------------------------------------------------------------------------
#define ATT_QH 0
#define ATT_QL 16384
#define ATT_STG0 32768
#define ATT_STG_B 32768
#define ATT_SMEM (32768 + 2 * ATT_STG_B)   // 98304

__global__ __launch_bounds__(256, 2) void attn_kernel(const float* __restrict__ gm)
{
    extern __shared__ __align__(16) char smem[];
    const uint32_t sb = s2u(smem);
    const int tid  = threadIdx.x;
    const int lane = tid & 31;
    const int w    = tid >> 5;
    const int h    = blockIdx.x;
    const int q0   = blockIdx.y * 128;
    const int b    = blockIdx.z;
    const int bh   = b * NHEAD + h;

    const __nv_bfloat16* Qh = g_oqh + ((size_t)bh * SEQ + q0) * DHEAD;
    const __nv_bfloat16* Ql = g_oql + ((size_t)bh * SEQ + q0) * DHEAD;
    const __nv_bfloat16* Kh = g_okh + (size_t)bh * SEQ * DHEAD;
    const __nv_bfloat16* Kl = g_okl + (size_t)bh * SEQ * DHEAD;
    const __nv_bfloat16* Vh = g_ovh + (size_t)bh * SEQ * DHEAD;
    const __nv_bfloat16* Vl = g_ovl + (size_t)bh * SEQ * DHEAD;

#pragma unroll
    for (int i = 0; i < 4; i++) {
        const int c = tid + i * 256;
        const int r = c >> 3, off = c & 7;
        const uint32_t d = swz((uint32_t)r * 128 + off * 16);
        cp16(sb + ATT_QH + d, Qh + (size_t)r * DHEAD + off * 8);
        cp16(sb + ATT_QL + d, Ql + (size_t)r * DHEAD + off * 8);
    }
    auto load_stage = [&](int kt, int s) {
        const int k0 = kt * 64;
        const uint32_t base = sb + ATT_STG0 + (uint32_t)s * ATT_STG_B;
#pragma unroll
        for (int i = 0; i < 2; i++) {
            const int c = tid + i * 256;
            const int r = c >> 3, off = c & 7;
            const uint32_t d = swz((uint32_t)r * 128 + off * 16);
            const size_t g = (size_t)(k0 + r) * DHEAD + off * 8;
            cp16(base + d,         Kh + g);
            cp16(base + 8192 + d,  Kl + g);
            cp16(base + 16384 + d, Vh + g);
            cp16(base + 24576 + d, Vl + g);
        }
    };
    load_stage(0, 0);
    asm volatile("cp.async.commit_group;" ::: "memory");
    load_stage(1, 1);
    asm volatile("cp.async.commit_group;" ::: "memory");
    asm volatile("cp.async.wait_group 1;" ::: "memory");
    __syncthreads();

    const int l8 = lane & 7, lg = lane >> 3;
    const int a_row_off = ((lg & 1) ? 8 : 0) + l8;
    const int a_col_off = (lg & 2) ? 8 : 0;
    const int b_row_off = ((lg >> 1) ? 8 : 0) + l8;
    const int b_col_off = (lg & 1) ? 8 : 0;

    uint32_t qfh[4][4];
    const uint32_t qrowbyte = (uint32_t)(w * 16 + a_row_off) * 128;
#pragma unroll
    for (int ks = 0; ks < 4; ks++) {
        const uint32_t d = swz(qrowbyte + (ks * 16 + a_col_off) * 2);
        ldm_x4(qfh[ks], sb + ATT_QH + d);
    }

    float accv[8][4];
#pragma unroll
    for (int i = 0; i < 8; i++)
#pragma unroll
        for (int j = 0; j < 4; j++) accv[i][j] = 0.0f;
    float m0 = -INFINITY, m1 = -INFINITY, l0 = 0.0f, l1 = 0.0f;

    const int r0 = lane >> 2;
    const int qrow0 = q0 + w * 16 + r0;
    const float* gmRow0 = gm + ((size_t)b * SEQ + qrow0) * SEQ;
    const float* gmRow1 = gmRow0 + 8 * SEQ;
    const int colq = (lane & 3) * 2;

    for (int kt = 0; kt < SEQ / 64; kt++) {
        const int st = kt & 1;
        const uint32_t stg = sb + ATT_STG0 + (uint32_t)st * ATT_STG_B;

        float s[8][4];
#pragma unroll
        for (int i = 0; i < 8; i++)
#pragma unroll
            for (int j = 0; j < 4; j++) s[i][j] = 0.0f;
#pragma unroll
        for (int ks = 0; ks < 4; ks++) {
            uint32_t qfl[4];
            ldm_x4(qfl, sb + ATT_QL + swz(qrowbyte + (ks * 16 + a_col_off) * 2));
#pragma unroll
            for (int g16 = 0; g16 < 4; g16++) {
                const int row = g16 * 16 + b_row_off;
                const int col = ks * 16 + b_col_off;
                const uint32_t d = swz((uint32_t)row * 128 + col * 2);
                uint32_t kh4[4], kl4[4];
                ldm_x4(kh4, stg + d);
                ldm_x4(kl4, stg + 8192 + d);
                uint32_t bh0[2] = {kh4[0], kh4[1]}, bh1[2] = {kh4[2], kh4[3]};
                uint32_t bl0[2] = {kl4[0], kl4[1]}, bl1[2] = {kl4[2], kl4[3]};
                mma_bf16(s[g16 * 2],     qfh[ks], bh0);
                mma_bf16(s[g16 * 2],     qfh[ks], bl0);
                mma_bf16(s[g16 * 2],     qfl,     bh0);
                mma_bf16(s[g16 * 2 + 1], qfh[ks], bh1);
                mma_bf16(s[g16 * 2 + 1], qfh[ks], bl1);
                mma_bf16(s[g16 * 2 + 1], qfl,     bh1);
            }
        }

        float rm0 = -INFINITY, rm1 = -INFINITY;
#pragma unroll
        for (int nt = 0; nt < 8; nt++) {
            rm0 = fmaxf(rm0, fmaxf(s[nt][0], s[nt][1]));
            rm1 = fmaxf(rm1, fmaxf(s[nt][2], s[nt][3]));
        }
        rm0 = fmaxf(rm0, __shfl_xor_sync(0xffffffffu, rm0, 1));
        rm0 = fmaxf(rm0, __shfl_xor_sync(0xffffffffu, rm0, 2));
        rm1 = fmaxf(rm1, __shfl_xor_sync(0xffffffffu, rm1, 1));
        rm1 = fmaxf(rm1, __shfl_xor_sync(0xffffffffu, rm1, 2));
        const float m0n = fmaxf(m0, rm0);
        const float m1n = fmaxf(m1, rm1);
        const float c0 = ex2(m0 - m0n);
        const float c1 = ex2(m1 - m1n);
        l0 *= c0; l1 *= c1;
        m0 = m0n; m1 = m1n;
#pragma unroll
        for (int nt = 0; nt < 8; nt++) {
            accv[nt][0] *= c0; accv[nt][1] *= c0;
            accv[nt][2] *= c1; accv[nt][3] *= c1;
        }

        uint32_t aPh[4][4], aPl[4][4];
        const int kbase = kt * 64 + colq;
#pragma unroll
        for (int nt = 0; nt < 8; nt++) {
            const int kc = kbase + nt * 8;
            const float2 g0 = *(const float2*)(gmRow0 + kc);
            const float2 g1 = *(const float2*)(gmRow1 + kc);
            const float p00 = ex2(s[nt][0] - m0);
            const float p01 = ex2(s[nt][1] - m0);
            const float p10 = ex2(s[nt][2] - m1);
            const float p11 = ex2(s[nt][3] - m1);
            l0 += (g0.x >= 0.0f ? p00 : 0.0f) + (g0.y >= 0.0f ? p01 : 0.0f);
            l1 += (g1.x >= 0.0f ? p10 : 0.0f) + (g1.y >= 0.0f ? p11 : 0.0f);
            const float w00 = p00 * fmaxf(g0.x, 0.0f);
            const float w01 = p01 * fmaxf(g0.y, 0.0f);
            const float w10 = p10 * fmaxf(g1.x, 0.0f);
            const float w11 = p11 * fmaxf(g1.y, 0.0f);
            const int ks = nt >> 1, half = (nt & 1) * 2;
            split2(w00, w01, aPh[ks][half + 0], aPl[ks][half + 0]);
            split2(w10, w11, aPh[ks][half + 1], aPl[ks][half + 1]);
        }

#pragma unroll
        for (int ks = 0; ks < 4; ks++) {
#pragma unroll
            for (int ng = 0; ng < 4; ng++) {
                const int row = ks * 16 + ((lg & 1) ? 8 : 0) + l8;
                const int col = ng * 16 + ((lg >> 1) ? 8 : 0);
                const uint32_t d = swz((uint32_t)row * 128 + col * 2);
                uint32_t vh4[4], vl4[4];
                ldm_x4_t(vh4, stg + 16384 + d);
                ldm_x4_t(vl4, stg + 24576 + d);
                uint32_t bh0[2] = {vh4[0], vh4[1]}, bh1[2] = {vh4[2], vh4[3]};
                uint32_t bl0[2] = {vl4[0], vl4[1]}, bl1[2] = {vl4[2], vl4[3]};
                mma_bf16(accv[ng * 2],     aPh[ks], bh0);
                mma_bf16(accv[ng * 2],     aPh[ks], bl0);
                mma_bf16(accv[ng * 2],     aPl[ks], bh0);
                mma_bf16(accv[ng * 2 + 1], aPh[ks], bh1);
                mma_bf16(accv[ng * 2 + 1], aPh[ks], bl1);
                mma_bf16(accv[ng * 2 + 1], aPl[ks], bh1);
            }
        }

        __syncthreads();
        if (kt + 2 < SEQ / 64) load_stage(kt + 2, st);
        asm volatile("cp.async.commit_group;" ::: "memory");
        if (kt + 1 < SEQ / 64) {
            asm volatile("cp.async.wait_group 1;" ::: "memory");
            __syncthreads();
        }
    }

    l0 += __shfl_xor_sync(0xffffffffu, l0, 1);
    l0 += __shfl_xor_sync(0xffffffffu, l0, 2);
    l1 += __shfl_xor_sync(0xffffffffu, l1, 1);
    l1 += __shfl_xor_sync(0xffffffffu, l1, 2);
    const float inv0 = 1.0f / l0, inv1 = 1.0f / l1;

    const size_t tok0 = (size_t)b * SEQ + qrow0;
    __nv_bfloat16* ch0 = g_ch + tok0 * DMODEL + h * DHEAD + colq;
    __nv_bfloat16* cl0 = g_cl + tok0 * DMODEL + h * DHEAD + colq;
#pragma unroll
    for (int nt = 0; nt < 8; nt++) {
        uint32_t hi, lo;
        split2(accv[nt][0] * inv0, accv[nt][1] * inv0, hi, lo);
        *(uint32_t*)(ch0 + nt * 8) = hi;
        *(uint32_t*)(cl0 + nt * 8) = lo;
        split2(accv[nt][2] * inv1, accv[nt][3] * inv1, hi, lo);
        *(uint32_t*)(ch0 + 8 * DMODEL + nt * 8) = hi;
        *(uint32_t*)(cl0 + 8 * DMODEL + nt * 8) = lo;
    }
}

// ---------------------------------------------------------------------------
extern "C" void kernel_launch(void* const* d_in, const int* in_sizes, int n_in,
                              void* d_out, int out_size)
{
    (void)in_sizes; (void)n_in; (void)out_size;
    const float* query = (const float*)d_in[0];
    const float* key_  = (const float*)d_in[1];
    const float* value = (const float*)d_in[2];
    const int*   mask  = (const int*)  d_in[3];
    const float* group = (const float*)d_in[4];
    const float* Wq = (const float*)d_in[5];
    const float* bq = (const float*)d_in[6];
    const float* Wk = (const float*)d_in[7];
    const float* bk = (const float*)d_in[8];
    const float* Wv = (const float*)d_in[9];
    const float* bv = (const float*)d_in[10];
    const float* Wo = (const float*)d_in[11];
    const float* bo = (const float*)d_in[12];
    float* out = (float*)d_out;

    float* gmp;
    cudaGetSymbolAddress((void**)&gmp, g_gm);

    cudaFuncSetAttribute(gemm_qkv_kernel, cudaFuncAttributeMaxDynamicSharedMemorySize,
                         GEMM_SMEM);
    cudaFuncSetAttribute(gemm_out_kernel, cudaFuncAttributeMaxDynamicSharedMemorySize,
                         GEMM_SMEM);
    cudaFuncSetAttribute(attn_kernel, cudaFuncAttributeMaxDynamicSharedMemorySize,
                         ATT_SMEM);

    cvt_act_kernel<<<dim3(NTOK * (DMODEL / 8) / 256, 3), 256>>>(query, key_, value);
    cvt_w_kernel<<<dim3(DMODEL * (DMODEL / 8) / 256, 4), 256>>>(Wq, Wk, Wv, Wo);
    prep_gm_kernel<<<BATCH * SEQ * SEQ / 4 / 256, 256>>>(mask, group, gmp);

    const float QSCALE = 0.125f * 1.44269504088896f;  // 1/sqrt(DK) * log2(e)
    gemm_qkv_kernel<<<dim3(DMODEL / BN, NTOK / BM, 3), 256, GEMM_SMEM>>>(
        bq, bk, bv, QSCALE);

    attn_kernel<<<dim3(NHEAD, SEQ / 128, BATCH), 256, ATT_SMEM>>>(gmp);

    gemm_out_kernel<<<dim3(DMODEL / BN, NTOK / BM), 256, GEMM_SMEM>>>(bo, out);
}